// round 1
// baseline (speedup 1.0000x reference)
#include <cuda_runtime.h>
#include <math.h>

#define B_   64
#define N_   197
#define C_   768
#define H_   12
#define DH_  64
#define R_   98
#define K_   99      // kept tokens incl CLS
#define NKEPT_ 98    // kept image tokens
#define THRK_ 1941   // 1-indexed rank of threshold (thr_idx=1940)
#define ALPHA_ 0.1f
#define EPS_ 1e-5f

// ---------------- scratch (device globals; no allocation allowed) ----------------
__device__ float g_h   [(size_t)B_*N_*C_];
__device__ float g_qkv [(size_t)B_*N_*3*C_];
__device__ float g_attn[(size_t)B_*H_*N_*N_];
__device__ float g_ao  [(size_t)B_*N_*C_];
__device__ float g_x1  [(size_t)B_*N_*C_];
__device__ float g_x2  [(size_t)B_*K_*C_];
__device__ float g_h2  [(size_t)B_*K_*C_];
__device__ float g_mlp [(size_t)B_*K_*4*C_];
__device__ int   g_ik  [B_*K_];
__device__ int   g_ie  [B_*R_];

// ---------------- LayerNorm: one block per row, C=768=3*256 ----------------
__global__ void ln_kernel(const float* __restrict__ x, const float* __restrict__ g,
                          const float* __restrict__ bta, float* __restrict__ o)
{
    int row = blockIdx.x;
    const float* xr = x + (size_t)row * C_;
    float* orow = o + (size_t)row * C_;
    float v[3]; float s = 0.f, ss = 0.f;
#pragma unroll
    for (int i = 0; i < 3; i++) {
        v[i] = xr[threadIdx.x + 256 * i];
        s += v[i]; ss = fmaf(v[i], v[i], ss);
    }
    for (int off = 16; off; off >>= 1) {
        s  += __shfl_xor_sync(0xffffffffu, s, off);
        ss += __shfl_xor_sync(0xffffffffu, ss, off);
    }
    __shared__ float rs[8], rss[8];
    __shared__ float smean, srstd;
    int w = threadIdx.x >> 5;
    if ((threadIdx.x & 31) == 0) { rs[w] = s; rss[w] = ss; }
    __syncthreads();
    if (threadIdx.x == 0) {
        float S = 0.f, SS = 0.f;
        for (int i = 0; i < 8; i++) { S += rs[i]; SS += rss[i]; }
        float mean = S * (1.f / C_);
        float var = SS * (1.f / C_) - mean * mean;
        smean = mean; srstd = rsqrtf(var + EPS_);
    }
    __syncthreads();
    float mean = smean, rstd = srstd;
#pragma unroll
    for (int i = 0; i < 3; i++) {
        int c = threadIdx.x + 256 * i;
        orow[c] = (v[i] - mean) * rstd * g[c] + bta[c];
    }
}

// ---------------- generic SGEMM 64x128x16, 256 thr, 4x8/thread ----------------
// C = A[M,K] @ B[K,N]  (+bias)(+gelu)(+res). Requires M%64==0, N%128==0, K%16==0.
template<bool GELU, bool HASBIAS, bool HASRES>
__global__ void sgemm_kernel(const float* __restrict__ A, const float* __restrict__ Bm,
                             const float* __restrict__ bias, const float* __restrict__ res,
                             float* __restrict__ Co, int M, int Nd, int Kd)
{
    __shared__ float As[16][68];    // transposed A tile, odd-ish pad -> conflict-free
    __shared__ float Bs[16][132];
    int tid = threadIdx.x;
    int tx = tid & 15, ty = tid >> 4;
    int m0 = blockIdx.y * 64, n0 = blockIdx.x * 128;
    float acc[4][8];
#pragma unroll
    for (int i = 0; i < 4; i++)
#pragma unroll
        for (int j = 0; j < 8; j++) acc[i][j] = 0.f;

    for (int k0 = 0; k0 < Kd; k0 += 16) {
#pragma unroll
        for (int r = 0; r < 4; r++) {        // A: 64x16 = 1024 elems
            int idx = tid + r * 256;
            int kk = idx & 15, mm = idx >> 4;
            As[kk][mm] = A[(size_t)(m0 + mm) * Kd + k0 + kk];
        }
#pragma unroll
        for (int r = 0; r < 8; r++) {        // B: 16x128 = 2048 elems
            int idx = tid + r * 256;
            int nn = idx & 127, kk = idx >> 7;
            Bs[kk][nn] = Bm[(size_t)(k0 + kk) * Nd + n0 + nn];
        }
        __syncthreads();
#pragma unroll
        for (int kk = 0; kk < 16; kk++) {
            float4 a  = *(const float4*)&As[kk][ty * 4];
            float4 b0 = *(const float4*)&Bs[kk][tx * 8];
            float4 b1 = *(const float4*)&Bs[kk][tx * 8 + 4];
            float av[4] = {a.x, a.y, a.z, a.w};
            float bv[8] = {b0.x, b0.y, b0.z, b0.w, b1.x, b1.y, b1.z, b1.w};
#pragma unroll
            for (int i = 0; i < 4; i++)
#pragma unroll
                for (int j = 0; j < 8; j++)
                    acc[i][j] = fmaf(av[i], bv[j], acc[i][j]);
        }
        __syncthreads();
    }

    float bvv[8];
    if (HASBIAS) {
#pragma unroll
        for (int j = 0; j < 8; j++) bvv[j] = bias[n0 + tx * 8 + j];
    }
#pragma unroll
    for (int i = 0; i < 4; i++) {
        int m = m0 + ty * 4 + i;
        size_t base = (size_t)m * Nd + n0 + tx * 8;
#pragma unroll
        for (int j = 0; j < 8; j++) {
            float c = acc[i][j];
            if (HASBIAS) c += bvv[j];
            if (GELU) c = 0.5f * c * (1.f + erff(c * 0.70710678118654752f));
            if (HASRES) c += res[base + j];
            Co[base + j] = c;
        }
    }
}

// ---------------- attention scores + softmax: block = (b,h, 8 queries) ----------------
__global__ void attn_score_kernel(const float* __restrict__ qkv, float* __restrict__ attn)
{
    __shared__ float Ks[32][65];
    __shared__ float qs[8][64];
    int bh = blockIdx.x;
    int b = bh / H_, hh = bh % H_;
    int tid = threadIdx.x;
    int w = tid >> 5, lane = tid & 31;
    int qbase = blockIdx.y * 8;
#pragma unroll
    for (int i = 0; i < 2; i++) {
        int idx = tid + i * 256;
        int qw = idx >> 6, d = idx & 63;
        int q = qbase + qw;
        qs[qw][d] = (q < N_) ? qkv[(size_t)(b * N_ + q) * 2304 + hh * 64 + d] * 0.125f : 0.f;
    }
    int q = qbase + w;
    float sc[7];
#pragma unroll
    for (int c = 0; c < 7; c++) {
        __syncthreads();
#pragma unroll
        for (int i = 0; i < 8; i++) {
            int idx = tid + i * 256;
            int r = idx >> 6, d = idx & 63;
            int kj = c * 32 + r;
            Ks[r][d] = (kj < N_) ? qkv[(size_t)(b * N_ + kj) * 2304 + 768 + hh * 64 + d] : 0.f;
        }
        __syncthreads();
        float s = 0.f;
#pragma unroll
        for (int d = 0; d < 64; d++) s = fmaf(qs[w][d], Ks[lane][d], s);
        int kj = c * 32 + lane;
        sc[c] = (kj < N_) ? s : -1e30f;
    }
    float mx = sc[0];
#pragma unroll
    for (int c = 1; c < 7; c++) mx = fmaxf(mx, sc[c]);
    for (int off = 16; off; off >>= 1) mx = fmaxf(mx, __shfl_xor_sync(0xffffffffu, mx, off));
    float sum = 0.f;
#pragma unroll
    for (int c = 0; c < 7; c++) { float e = expf(sc[c] - mx); sc[c] = e; sum += e; }
    for (int off = 16; off; off >>= 1) sum += __shfl_xor_sync(0xffffffffu, sum, off);
    float inv = 1.f / sum;
    if (q < N_) {
        float* arow = attn + ((size_t)bh * N_ + q) * N_;
#pragma unroll
        for (int c = 0; c < 7; c++) {
            int kj = c * 32 + lane;
            if (kj < N_) arow[kj] = sc[c] * inv;
        }
    }
}

// ---------------- attn @ V: block per (b,h), V in dynamic shared ----------------
__global__ void attn_av_kernel(const float* __restrict__ qkv, const float* __restrict__ attn,
                               float* __restrict__ ao)
{
    extern __shared__ float Vs[];   // N_*64 floats
    int bh = blockIdx.x;
    int b = bh / H_, hh = bh % H_;
    int tid = threadIdx.x;
    for (int idx = tid; idx < N_ * 64; idx += 256) {
        int m = idx >> 6, d = idx & 63;
        Vs[idx] = qkv[(size_t)(b * N_ + m) * 2304 + 1536 + hh * 64 + d];
    }
    __syncthreads();
    int d = tid & 63, qg = tid >> 6;
    for (int q = qg; q < N_; q += 4) {
        const float* arow = attn + ((size_t)bh * N_ + q) * N_;
        float acc = 0.f;
        int m = 0;
        for (; m + 4 <= N_; m += 4) {
            acc = fmaf(arow[m],     Vs[m * 64 + d],       acc);
            acc = fmaf(arow[m + 1], Vs[(m + 1) * 64 + d], acc);
            acc = fmaf(arow[m + 2], Vs[(m + 2) * 64 + d], acc);
            acc = fmaf(arow[m + 3], Vs[(m + 3) * 64 + d], acc);
        }
        for (; m < N_; m++) acc = fmaf(arow[m], Vs[m * 64 + d], acc);
        ao[(size_t)(b * N_ + q) * 768 + hh * 64 + d] = acc;
    }
}

// ---------------- selection: head-mean attn diagonal, stable descending rank ------------
__global__ void select_kernel(const float* __restrict__ attn, int* __restrict__ ik,
                              int* __restrict__ ie)
{
    __shared__ float diag[196];
    __shared__ int kept[196];
    int b = blockIdx.x, tid = threadIdx.x;
    if (tid < 196) {
        float s = 0.f;
        for (int hh = 0; hh < H_; hh++)
            s += attn[((size_t)(b * H_ + hh) * N_ + (tid + 1)) * N_ + (tid + 1)];
        diag[tid] = s;  // positive scale (mean vs sum) doesn't change ranking
    }
    __syncthreads();
    if (tid < 196) {
        float di = diag[tid];
        int rank = 0;
        for (int j = 0; j < 196; j++) {
            float dj = diag[j];
            rank += (dj > di) || (dj == di && j < tid);  // stable argsort(-diag)
        }
        kept[tid] = (rank < NKEPT_) ? 1 : 0;
    }
    __syncthreads();
    if (tid < 196) {
        int mine = kept[tid];
        int pos = 0;
        for (int j = 0; j < tid; j++) pos += (kept[j] == mine);
        if (mine) ik[b * K_ + 1 + pos] = tid + 1;     // sorted ascending by construction
        else      ie[b * R_ + pos]     = tid + 1;
    }
    if (tid == 0) ik[b * K_] = 0;                     // CLS token always kept, index 0
}

// ---------------- propagation: block per (b,h); exact threshold via bit bsearch --------
__global__ void propagate_kernel(const float* __restrict__ attn, const float* __restrict__ x1,
                                 const int* __restrict__ ikg, const int* __restrict__ ieg,
                                 float* __restrict__ x2)
{
    extern __shared__ float sm[];
    float* ws = sm;                 // K_*R_ = 9702
    float* xe = sm + K_ * R_;       // R_*64 = 6272
    __shared__ int ik[K_], ie[R_];
    __shared__ int cnt;
    int bh = blockIdx.x;
    int b = bh / H_, hh = bh % H_;
    int tid = threadIdx.x;
    if (tid < K_) ik[tid] = ikg[b * K_ + tid];
    if (tid < R_) ie[tid] = ieg[b * R_ + tid];
    __syncthreads();
    const float* ablk = attn + (size_t)bh * N_ * N_;
    for (int idx = tid; idx < K_ * R_; idx += 256) {
        int k = idx / R_, e = idx - k * R_;
        ws[idx] = ablk[(size_t)ik[k] * N_ + ie[e]];
    }
    for (int idx = tid; idx < R_ * 64; idx += 256) {
        int e = idx >> 6, d = idx & 63;
        xe[idx] = x1[(size_t)(b * N_ + ie[e]) * 768 + hh * 64 + d];
    }
    __syncthreads();

    // threshold = THRK_-th largest of ws (exact element value).
    // softmax weights are >= 0, so uint order == float order: binary search on bits.
    unsigned lo = 0u, hi = 0x7f7fffffu;
    while (lo < hi) {
        unsigned mid = lo + ((hi - lo + 1) >> 1);
        if (tid == 0) cnt = 0;
        __syncthreads();
        int local = 0;
        for (int i = tid; i < K_ * R_; i += 256)
            local += (__float_as_uint(ws[i]) >= mid);
        for (int off = 16; off; off >>= 1) local += __shfl_xor_sync(0xffffffffu, local, off);
        if ((tid & 31) == 0) atomicAdd(&cnt, local);
        __syncthreads();
        int c = cnt;
        __syncthreads();
        if (c >= THRK_) lo = mid; else hi = mid - 1;
    }
    float thr = __uint_as_float(lo);

    for (int p = tid; p < K_ * 64; p += 256) {
        int k = p >> 6, d = p & 63;
        const float* wr = ws + k * R_;
        float acc = 0.f;
#pragma unroll 2
        for (int e = 0; e < R_; e++) {
            float wv = wr[e];
            wv = (wv >= thr) ? wv : 0.f;
            acc = fmaf(wv, xe[e * 64 + d], acc);
        }
        x2[(size_t)(b * K_ + k) * 768 + hh * 64 + d] =
            x1[(size_t)(b * N_ + ik[k]) * 768 + hh * 64 + d] + ALPHA_ * acc;
    }
}

// ---------------- host ----------------
extern "C" void kernel_launch(void* const* d_in, const int* in_sizes, int n_in,
                              void* d_out, int out_size)
{
    const float* x     = (const float*)d_in[0];
    const float* n1g   = (const float*)d_in[1];
    const float* n1b   = (const float*)d_in[2];
    const float* qkvw  = (const float*)d_in[3];
    const float* projw = (const float*)d_in[4];
    const float* projb = (const float*)d_in[5];
    const float* n2g   = (const float*)d_in[6];
    const float* n2b   = (const float*)d_in[7];
    const float* fc1w  = (const float*)d_in[8];
    const float* fc1b  = (const float*)d_in[9];
    const float* fc2w  = (const float*)d_in[10];
    const float* fc2b  = (const float*)d_in[11];
    float* out = (float*)d_out;

    float *h, *qkv, *attn, *ao, *x1, *x2, *h2, *mlp;
    int *ik, *ie;
    cudaGetSymbolAddress((void**)&h,    g_h);
    cudaGetSymbolAddress((void**)&qkv,  g_qkv);
    cudaGetSymbolAddress((void**)&attn, g_attn);
    cudaGetSymbolAddress((void**)&ao,   g_ao);
    cudaGetSymbolAddress((void**)&x1,   g_x1);
    cudaGetSymbolAddress((void**)&x2,   g_x2);
    cudaGetSymbolAddress((void**)&h2,   g_h2);
    cudaGetSymbolAddress((void**)&mlp,  g_mlp);
    cudaGetSymbolAddress((void**)&ik,   g_ik);
    cudaGetSymbolAddress((void**)&ie,   g_ie);

    const int AV_SMEM   = N_ * 64 * 4;                  // 50432 B
    const int PROP_SMEM = (K_ * R_ + R_ * 64) * 4;      // 63896 B
    cudaFuncSetAttribute(attn_av_kernel,   cudaFuncAttributeMaxDynamicSharedMemorySize, AV_SMEM);
    cudaFuncSetAttribute(propagate_kernel, cudaFuncAttributeMaxDynamicSharedMemorySize, PROP_SMEM);

    // 1. LN1
    ln_kernel<<<B_ * N_, 256>>>(x, n1g, n1b, h);
    // 2. QKV GEMM: [12608,768] @ [768,2304]
    sgemm_kernel<false, false, false><<<dim3(2304 / 128, 12608 / 64), 256>>>(
        h, qkvw, nullptr, nullptr, qkv, B_ * N_, 3 * C_, C_);
    // 3. attention scores + softmax
    attn_score_kernel<<<dim3(B_ * H_, (N_ + 7) / 8), 256>>>(qkv, attn);
    // 4. attn @ V
    attn_av_kernel<<<B_ * H_, 256, AV_SMEM>>>(qkv, attn, ao);
    // 5. proj + bias + residual(x)
    sgemm_kernel<false, true, true><<<dim3(768 / 128, 12608 / 64), 256>>>(
        ao, projw, projb, x, x1, B_ * N_, C_, C_);
    // 6. token selection
    select_kernel<<<B_, 256>>>(attn, ik, ie);
    // 7. thresholded graph propagation
    propagate_kernel<<<B_ * H_, 256, PROP_SMEM>>>(attn, x1, ik, ie, x2);
    // 8. LN2
    ln_kernel<<<B_ * K_, 256>>>(x2, n2g, n2b, h2);
    // 9. fc1 + bias + exact gelu: [6336,768] @ [768,3072]
    sgemm_kernel<true, true, false><<<dim3(3072 / 128, 6336 / 64), 256>>>(
        h2, fc1w, fc1b, nullptr, mlp, B_ * K_, 4 * C_, C_);
    // 10. fc2 + bias + residual(x2) -> out
    sgemm_kernel<false, true, true><<<dim3(768 / 128, 6336 / 64), 256>>>(
        mlp, fc2w, fc2b, x2, out, B_ * K_, C_, 4 * C_);
}

// round 2
// speedup vs baseline: 1.1535x; 1.1535x over previous
#include <cuda_runtime.h>
#include <math.h>

#define B_   64
#define N_   197
#define C_   768
#define H_   12
#define DH_  64
#define R_   98
#define K_   99
#define NKEPT_ 98
#define THRK_ 1941
#define ALPHA_ 0.1f
#define EPS_ 1e-5f

// ---------------- scratch ----------------
__device__ float g_h   [(size_t)B_*N_*C_];
__device__ float g_qkv [(size_t)B_*N_*3*C_];
__device__ float g_attn[(size_t)B_*H_*N_*N_];
__device__ float g_ao  [(size_t)B_*N_*C_];
__device__ float g_x1  [(size_t)B_*N_*C_];
__device__ float g_x2  [(size_t)B_*K_*C_];
__device__ float g_h2  [(size_t)B_*K_*C_];
__device__ float g_mlp [(size_t)B_*K_*4*C_];
__device__ int   g_ik  [B_*K_];
__device__ int   g_ie  [B_*R_];

// ---------------- LayerNorm ----------------
__global__ void ln_kernel(const float* __restrict__ x, const float* __restrict__ g,
                          const float* __restrict__ bta, float* __restrict__ o)
{
    int row = blockIdx.x;
    const float* xr = x + (size_t)row * C_;
    float* orow = o + (size_t)row * C_;
    float v[3]; float s = 0.f, ss = 0.f;
#pragma unroll
    for (int i = 0; i < 3; i++) {
        v[i] = xr[threadIdx.x + 256 * i];
        s += v[i]; ss = fmaf(v[i], v[i], ss);
    }
    for (int off = 16; off; off >>= 1) {
        s  += __shfl_xor_sync(0xffffffffu, s, off);
        ss += __shfl_xor_sync(0xffffffffu, ss, off);
    }
    __shared__ float rs[8], rss[8];
    __shared__ float smean, srstd;
    int w = threadIdx.x >> 5;
    if ((threadIdx.x & 31) == 0) { rs[w] = s; rss[w] = ss; }
    __syncthreads();
    if (threadIdx.x == 0) {
        float S = 0.f, SS = 0.f;
        for (int i = 0; i < 8; i++) { S += rs[i]; SS += rss[i]; }
        float mean = S * (1.f / C_);
        float var = SS * (1.f / C_) - mean * mean;
        smean = mean; srstd = rsqrtf(var + EPS_);
    }
    __syncthreads();
    float mean = smean, rstd = srstd;
#pragma unroll
    for (int i = 0; i < 3; i++) {
        int c = threadIdx.x + 256 * i;
        orow[c] = (v[i] - mean) * rstd * g[c] + bta[c];
    }
}

// ---------------- SGEMM 64x128x16, double-buffered, float4 loads ----------------
template<bool GELU, bool HASBIAS, bool HASRES>
__global__ void sgemm_kernel(const float* __restrict__ A, const float* __restrict__ Bm,
                             const float* __restrict__ bias, const float* __restrict__ res,
                             float* __restrict__ Co, int M, int Nd, int Kd)
{
    __shared__ float As[2][16][68];
    __shared__ float Bs[2][16][132];
    int tid = threadIdx.x;
    int tx = tid & 15, ty = tid >> 4;
    int m0 = blockIdx.y * 64, n0 = blockIdx.x * 128;

    int arow = tid >> 2;
    int acol = (tid & 3) * 4;
    const float* Aptr = A + (size_t)(m0 + arow) * Kd + acol;
    int kk0 = tid >> 5,           nn0 = (tid & 31) * 4;
    int kk1 = (tid + 256) >> 5,   nn1 = nn0;
    const float* Bptr = Bm + n0;

    float acc[4][8];
#pragma unroll
    for (int i = 0; i < 4; i++)
#pragma unroll
        for (int j = 0; j < 8; j++) acc[i][j] = 0.f;

    // prologue
    {
        float4 a = *(const float4*)(Aptr);
        As[0][acol + 0][arow] = a.x;
        As[0][acol + 1][arow] = a.y;
        As[0][acol + 2][arow] = a.z;
        As[0][acol + 3][arow] = a.w;
        float4 b0 = *(const float4*)(Bptr + (size_t)kk0 * Nd + nn0);
        float4 b1 = *(const float4*)(Bptr + (size_t)kk1 * Nd + nn1);
        *(float4*)&Bs[0][kk0][nn0] = b0;
        *(float4*)&Bs[0][kk1][nn1] = b1;
    }
    __syncthreads();

    int buf = 0;
    for (int k0 = 16; k0 < Kd; k0 += 16) {
        float4 an = *(const float4*)(Aptr + k0);
        float4 b0 = *(const float4*)(Bptr + (size_t)(k0 + kk0) * Nd + nn0);
        float4 b1 = *(const float4*)(Bptr + (size_t)(k0 + kk1) * Nd + nn1);

        const float (*Ac)[68]  = As[buf];
        const float (*Bc)[132] = Bs[buf];
#pragma unroll
        for (int kk = 0; kk < 16; kk++) {
            float4 a  = *(const float4*)&Ac[kk][ty * 4];
            float4 c0 = *(const float4*)&Bc[kk][tx * 8];
            float4 c1 = *(const float4*)&Bc[kk][tx * 8 + 4];
            float av[4] = {a.x, a.y, a.z, a.w};
            float bv[8] = {c0.x, c0.y, c0.z, c0.w, c1.x, c1.y, c1.z, c1.w};
#pragma unroll
            for (int i = 0; i < 4; i++)
#pragma unroll
                for (int j = 0; j < 8; j++)
                    acc[i][j] = fmaf(av[i], bv[j], acc[i][j]);
        }

        int nb = buf ^ 1;
        As[nb][acol + 0][arow] = an.x;
        As[nb][acol + 1][arow] = an.y;
        As[nb][acol + 2][arow] = an.z;
        As[nb][acol + 3][arow] = an.w;
        *(float4*)&Bs[nb][kk0][nn0] = b0;
        *(float4*)&Bs[nb][kk1][nn1] = b1;
        __syncthreads();
        buf = nb;
    }
    {
        const float (*Ac)[68]  = As[buf];
        const float (*Bc)[132] = Bs[buf];
#pragma unroll
        for (int kk = 0; kk < 16; kk++) {
            float4 a  = *(const float4*)&Ac[kk][ty * 4];
            float4 c0 = *(const float4*)&Bc[kk][tx * 8];
            float4 c1 = *(const float4*)&Bc[kk][tx * 8 + 4];
            float av[4] = {a.x, a.y, a.z, a.w};
            float bv[8] = {c0.x, c0.y, c0.z, c0.w, c1.x, c1.y, c1.z, c1.w};
#pragma unroll
            for (int i = 0; i < 4; i++)
#pragma unroll
                for (int j = 0; j < 8; j++)
                    acc[i][j] = fmaf(av[i], bv[j], acc[i][j]);
        }
    }

    float bvv[8];
    if (HASBIAS) {
#pragma unroll
        for (int j = 0; j < 8; j++) bvv[j] = bias[n0 + tx * 8 + j];
    }
#pragma unroll
    for (int i = 0; i < 4; i++) {
        int m = m0 + ty * 4 + i;
        size_t base = (size_t)m * Nd + n0 + tx * 8;
#pragma unroll
        for (int j = 0; j < 8; j++) {
            float c = acc[i][j];
            if (HASBIAS) c += bvv[j];
            if (GELU) c = 0.5f * c * (1.f + erff(c * 0.70710678118654752f));
            if (HASRES) c += res[base + j];
            Co[base + j] = c;
        }
    }
}

// ---------------- scores: S = (Q*scale) @ K^T, per (b,h), 64x64 tiles ----------------
__global__ void score_kernel(const float* __restrict__ qkv, float* __restrict__ attn)
{
    __shared__ float Qs[64][68];   // [d][m]
    __shared__ float Ks[64][68];   // [d][n]
    int bh = blockIdx.x;
    int b = bh / H_, hh = bh % H_;
    int m0 = blockIdx.y * 64, n0 = blockIdx.z * 64;
    int tid = threadIdx.x;

#pragma unroll
    for (int r = 0; r < 4; r++) {
        int i = tid + r * 256;
        int row = i >> 4, col4 = (i & 15) * 4;
        int mq = m0 + row, nk = n0 + row;
        float4 q = make_float4(0.f, 0.f, 0.f, 0.f);
        float4 k = make_float4(0.f, 0.f, 0.f, 0.f);
        if (mq < N_) q = *(const float4*)&qkv[(size_t)(b * N_ + mq) * 2304 + hh * 64 + col4];
        if (nk < N_) k = *(const float4*)&qkv[(size_t)(b * N_ + nk) * 2304 + 768 + hh * 64 + col4];
        Qs[col4 + 0][row] = q.x * 0.125f;
        Qs[col4 + 1][row] = q.y * 0.125f;
        Qs[col4 + 2][row] = q.z * 0.125f;
        Qs[col4 + 3][row] = q.w * 0.125f;
        Ks[col4 + 0][row] = k.x;
        Ks[col4 + 1][row] = k.y;
        Ks[col4 + 2][row] = k.z;
        Ks[col4 + 3][row] = k.w;
    }
    __syncthreads();

    int my = tid >> 4, nx = tid & 15;
    float acc[4][4];
#pragma unroll
    for (int i = 0; i < 4; i++)
#pragma unroll
        for (int j = 0; j < 4; j++) acc[i][j] = 0.f;
#pragma unroll
    for (int d = 0; d < 64; d++) {
        float4 a = *(const float4*)&Qs[d][my * 4];
        float4 bb = *(const float4*)&Ks[d][nx * 4];
        float av[4] = {a.x, a.y, a.z, a.w};
        float bv[4] = {bb.x, bb.y, bb.z, bb.w};
#pragma unroll
        for (int i = 0; i < 4; i++)
#pragma unroll
            for (int j = 0; j < 4; j++)
                acc[i][j] = fmaf(av[i], bv[j], acc[i][j]);
    }
#pragma unroll
    for (int i = 0; i < 4; i++) {
        int m = m0 + my * 4 + i;
        if (m >= N_) continue;
        float* arow = attn + ((size_t)bh * N_ + m) * N_;
#pragma unroll
        for (int j = 0; j < 4; j++) {
            int n = n0 + nx * 4 + j;
            if (n < N_) arow[n] = acc[i][j];
        }
    }
}

// ---------------- softmax: one warp per row ----------------
__global__ void softmax_kernel(float* __restrict__ attn)
{
    int row = blockIdx.x * 8 + (threadIdx.x >> 5);
    if (row >= B_ * H_ * N_) return;
    int lane = threadIdx.x & 31;
    float* arow = attn + (size_t)row * N_;
    float v[7];
    float mx = -1e30f;
#pragma unroll
    for (int c = 0; c < 7; c++) {
        int j = lane + c * 32;
        v[c] = (j < N_) ? arow[j] : -1e30f;
        mx = fmaxf(mx, v[c]);
    }
    for (int off = 16; off; off >>= 1) mx = fmaxf(mx, __shfl_xor_sync(0xffffffffu, mx, off));
    float sum = 0.f;
#pragma unroll
    for (int c = 0; c < 7; c++) { float e = expf(v[c] - mx); v[c] = e; sum += e; }
    for (int off = 16; off; off >>= 1) sum += __shfl_xor_sync(0xffffffffu, sum, off);
    float inv = 1.f / sum;
#pragma unroll
    for (int c = 0; c < 7; c++) {
        int j = lane + c * 32;
        if (j < N_) arow[j] = v[c] * inv;
    }
}

// ---------------- AV: O = attn @ V, per (b,h), 64-query tiles, 4x4 micro ----------------
__global__ void av_kernel(const float* __restrict__ qkv, const float* __restrict__ attn,
                          float* __restrict__ ao)
{
    __shared__ float As[32][68];   // [kk][m]
    __shared__ float Vs[32][68];   // [kk][d]
    int bh = blockIdx.x;
    int b = bh / H_, hh = bh % H_;
    int m0 = blockIdx.y * 64;
    int tid = threadIdx.x;
    int my = tid >> 4, nx = tid & 15;

    float acc[4][4];
#pragma unroll
    for (int i = 0; i < 4; i++)
#pragma unroll
        for (int j = 0; j < 4; j++) acc[i][j] = 0.f;

    for (int k0 = 0; k0 < N_; k0 += 32) {
#pragma unroll
        for (int r = 0; r < 8; r++) {
            int i = tid + r * 256;
            int kk = i & 31, mr = i >> 5;
            int m = m0 + mr, kj = k0 + kk;
            As[kk][mr] = (m < N_ && kj < N_) ? attn[((size_t)bh * N_ + m) * N_ + kj] : 0.f;
        }
#pragma unroll
        for (int r = 0; r < 8; r++) {
            int i = tid + r * 256;
            int d = i & 63, kk = i >> 6;
            int kj = k0 + kk;
            Vs[kk][d] = (kj < N_) ? qkv[(size_t)(b * N_ + kj) * 2304 + 1536 + hh * 64 + d] : 0.f;
        }
        __syncthreads();
#pragma unroll
        for (int kk = 0; kk < 32; kk++) {
            float4 a = *(const float4*)&As[kk][my * 4];
            float4 v = *(const float4*)&Vs[kk][nx * 4];
            float av[4] = {a.x, a.y, a.z, a.w};
            float vv[4] = {v.x, v.y, v.z, v.w};
#pragma unroll
            for (int i = 0; i < 4; i++)
#pragma unroll
                for (int j = 0; j < 4; j++)
                    acc[i][j] = fmaf(av[i], vv[j], acc[i][j]);
        }
        __syncthreads();
    }
#pragma unroll
    for (int i = 0; i < 4; i++) {
        int m = m0 + my * 4 + i;
        if (m >= N_) continue;
#pragma unroll
        for (int j = 0; j < 4; j++)
            ao[(size_t)(b * N_ + m) * 768 + hh * 64 + nx * 4 + j] = acc[i][j];
    }
}

// ---------------- selection ----------------
__global__ void select_kernel(const float* __restrict__ attn, int* __restrict__ ik,
                              int* __restrict__ ie)
{
    __shared__ float diag[196];
    __shared__ int kept[196];
    int b = blockIdx.x, tid = threadIdx.x;
    if (tid < 196) {
        float s = 0.f;
        for (int hh = 0; hh < H_; hh++)
            s += attn[((size_t)(b * H_ + hh) * N_ + (tid + 1)) * N_ + (tid + 1)];
        diag[tid] = s;
    }
    __syncthreads();
    if (tid < 196) {
        float di = diag[tid];
        int rank = 0;
        for (int j = 0; j < 196; j++) {
            float dj = diag[j];
            rank += (dj > di) || (dj == di && j < tid);
        }
        kept[tid] = (rank < NKEPT_) ? 1 : 0;
    }
    __syncthreads();
    if (tid < 196) {
        int mine = kept[tid];
        int pos = 0;
        for (int j = 0; j < tid; j++) pos += (kept[j] == mine);
        if (mine) ik[b * K_ + 1 + pos] = tid + 1;
        else      ie[b * R_ + pos]     = tid + 1;
    }
    if (tid == 0) ik[b * K_] = 0;
}

// ---------------- propagation ----------------
__global__ void propagate_kernel(const float* __restrict__ attn, const float* __restrict__ x1,
                                 const int* __restrict__ ikg, const int* __restrict__ ieg,
                                 float* __restrict__ x2)
{
    extern __shared__ float sm[];
    float* ws = sm;                 // K_*R_
    float* xe = sm + K_ * R_;       // R_*64
    __shared__ int ik[K_], ie[R_];
    __shared__ int cnt;
    int bh = blockIdx.x;
    int b = bh / H_, hh = bh % H_;
    int tid = threadIdx.x;
    if (tid < K_) ik[tid] = ikg[b * K_ + tid];
    if (tid < R_) ie[tid] = ieg[b * R_ + tid];
    __syncthreads();
    const float* ablk = attn + (size_t)bh * N_ * N_;
    for (int idx = tid; idx < K_ * R_; idx += 256) {
        int k = idx / R_, e = idx - k * R_;
        ws[idx] = ablk[(size_t)ik[k] * N_ + ie[e]];
    }
    for (int idx = tid; idx < R_ * 64; idx += 256) {
        int e = idx >> 6, d = idx & 63;
        xe[idx] = x1[(size_t)(b * N_ + ie[e]) * 768 + hh * 64 + d];
    }
    __syncthreads();

    unsigned lo = 0u, hi = 0x7f7fffffu;
    while (lo < hi) {
        unsigned mid = lo + ((hi - lo + 1) >> 1);
        if (tid == 0) cnt = 0;
        __syncthreads();
        int local = 0;
        for (int i = tid; i < K_ * R_; i += 256)
            local += (__float_as_uint(ws[i]) >= mid);
        for (int off = 16; off; off >>= 1) local += __shfl_xor_sync(0xffffffffu, local, off);
        if ((tid & 31) == 0) atomicAdd(&cnt, local);
        __syncthreads();
        int c = cnt;
        __syncthreads();
        if (c >= THRK_) lo = mid; else hi = mid - 1;
    }
    float thr = __uint_as_float(lo);

    for (int p = tid; p < K_ * 64; p += 256) {
        int k = p >> 6, d = p & 63;
        const float* wr = ws + k * R_;
        float acc = 0.f;
#pragma unroll 2
        for (int e = 0; e < R_; e++) {
            float wv = wr[e];
            wv = (wv >= thr) ? wv : 0.f;
            acc = fmaf(wv, xe[e * 64 + d], acc);
        }
        x2[(size_t)(b * K_ + k) * 768 + hh * 64 + d] =
            x1[(size_t)(b * N_ + ik[k]) * 768 + hh * 64 + d] + ALPHA_ * acc;
    }
}

// ---------------- host ----------------
extern "C" void kernel_launch(void* const* d_in, const int* in_sizes, int n_in,
                              void* d_out, int out_size)
{
    const float* x     = (const float*)d_in[0];
    const float* n1g   = (const float*)d_in[1];
    const float* n1b   = (const float*)d_in[2];
    const float* qkvw  = (const float*)d_in[3];
    const float* projw = (const float*)d_in[4];
    const float* projb = (const float*)d_in[5];
    const float* n2g   = (const float*)d_in[6];
    const float* n2b   = (const float*)d_in[7];
    const float* fc1w  = (const float*)d_in[8];
    const float* fc1b  = (const float*)d_in[9];
    const float* fc2w  = (const float*)d_in[10];
    const float* fc2b  = (const float*)d_in[11];
    float* out = (float*)d_out;

    float *h, *qkv, *attn, *ao, *x1, *x2, *h2, *mlp;
    int *ik, *ie;
    cudaGetSymbolAddress((void**)&h,    g_h);
    cudaGetSymbolAddress((void**)&qkv,  g_qkv);
    cudaGetSymbolAddress((void**)&attn, g_attn);
    cudaGetSymbolAddress((void**)&ao,   g_ao);
    cudaGetSymbolAddress((void**)&x1,   g_x1);
    cudaGetSymbolAddress((void**)&x2,   g_x2);
    cudaGetSymbolAddress((void**)&h2,   g_h2);
    cudaGetSymbolAddress((void**)&mlp,  g_mlp);
    cudaGetSymbolAddress((void**)&ik,   g_ik);
    cudaGetSymbolAddress((void**)&ie,   g_ie);

    const int PROP_SMEM = (K_ * R_ + R_ * 64) * 4;
    cudaFuncSetAttribute(propagate_kernel, cudaFuncAttributeMaxDynamicSharedMemorySize, PROP_SMEM);

    // 1. LN1
    ln_kernel<<<B_ * N_, 256>>>(x, n1g, n1b, h);
    // 2. QKV GEMM
    sgemm_kernel<false, false, false><<<dim3(2304 / 128, 12608 / 64), 256>>>(
        h, qkvw, nullptr, nullptr, qkv, B_ * N_, 3 * C_, C_);
    // 3. scores
    score_kernel<<<dim3(B_ * H_, 4, 4), 256>>>(qkv, attn);
    // 4. softmax
    softmax_kernel<<<(B_ * H_ * N_ + 7) / 8, 256>>>(attn);
    // 5. attn @ V
    av_kernel<<<dim3(B_ * H_, 4), 256>>>(qkv, attn, ao);
    // 6. proj + bias + residual
    sgemm_kernel<false, true, true><<<dim3(768 / 128, 12608 / 64), 256>>>(
        ao, projw, projb, x, x1, B_ * N_, C_, C_);
    // 7. selection
    select_kernel<<<B_, 256>>>(attn, ik, ie);
    // 8. propagation
    propagate_kernel<<<B_ * H_, 256, PROP_SMEM>>>(attn, x1, ik, ie, x2);
    // 9. LN2
    ln_kernel<<<B_ * K_, 256>>>(x2, n2g, n2b, h2);
    // 10. fc1 + gelu
    sgemm_kernel<true, true, false><<<dim3(3072 / 128, 6336 / 64), 256>>>(
        h2, fc1w, fc1b, nullptr, mlp, B_ * K_, 4 * C_, C_);
    // 11. fc2 + residual -> out
    sgemm_kernel<false, true, true><<<dim3(768 / 128, 6336 / 64), 256>>>(
        mlp, fc2w, fc2b, x2, out, B_ * K_, C_, 4 * C_);
}

// round 3
// speedup vs baseline: 2.5896x; 2.2450x over previous
#include <cuda_runtime.h>
#include <math.h>

#define B_   64
#define N_   197
#define C_   768
#define H_   12
#define DH_  64
#define R_   98
#define K_   99
#define NKEPT_ 98
#define THRK_ 1941
#define ALPHA_ 0.1f
#define EPS_ 1e-5f

// ---------------- scratch ----------------
__device__ float g_h   [(size_t)B_*N_*C_];
__device__ float g_qkv [(size_t)B_*N_*3*C_];
__device__ float g_attn[(size_t)B_*H_*N_*N_];
__device__ float g_ao  [(size_t)B_*N_*C_];
__device__ float g_x1  [(size_t)B_*N_*C_];
__device__ float g_x2  [(size_t)B_*K_*C_];
__device__ float g_h2  [(size_t)B_*K_*C_];
__device__ float g_mlp [(size_t)B_*K_*4*C_];
__device__ int   g_ik  [B_*K_];
__device__ int   g_ie  [B_*R_];

// ---------------- helpers ----------------
__device__ __forceinline__ unsigned f2tf32(float x) {
    unsigned r;
    asm("cvt.rna.tf32.f32 %0, %1;" : "=r"(r) : "f"(x));
    return r;
}
__device__ __forceinline__ void mma_tf32(float c[4], const unsigned a[4], const unsigned b[2]) {
    asm volatile(
        "mma.sync.aligned.m16n8k8.row.col.f32.tf32.tf32.f32 "
        "{%0,%1,%2,%3},{%4,%5,%6,%7},{%8,%9},{%0,%1,%2,%3};"
        : "+f"(c[0]), "+f"(c[1]), "+f"(c[2]), "+f"(c[3])
        : "r"(a[0]), "r"(a[1]), "r"(a[2]), "r"(a[3]), "r"(b[0]), "r"(b[1]));
}

// ---------------- LayerNorm ----------------
__global__ void ln_kernel(const float* __restrict__ x, const float* __restrict__ g,
                          const float* __restrict__ bta, float* __restrict__ o)
{
    int row = blockIdx.x;
    const float* xr = x + (size_t)row * C_;
    float* orow = o + (size_t)row * C_;
    float v[3]; float s = 0.f, ss = 0.f;
#pragma unroll
    for (int i = 0; i < 3; i++) {
        v[i] = xr[threadIdx.x + 256 * i];
        s += v[i]; ss = fmaf(v[i], v[i], ss);
    }
    for (int off = 16; off; off >>= 1) {
        s  += __shfl_xor_sync(0xffffffffu, s, off);
        ss += __shfl_xor_sync(0xffffffffu, ss, off);
    }
    __shared__ float rs[8], rss[8];
    __shared__ float smean, srstd;
    int w = threadIdx.x >> 5;
    if ((threadIdx.x & 31) == 0) { rs[w] = s; rss[w] = ss; }
    __syncthreads();
    if (threadIdx.x == 0) {
        float S = 0.f, SS = 0.f;
        for (int i = 0; i < 8; i++) { S += rs[i]; SS += rss[i]; }
        float mean = S * (1.f / C_);
        float var = SS * (1.f / C_) - mean * mean;
        smean = mean; srstd = rsqrtf(var + EPS_);
    }
    __syncthreads();
    float mean = smean, rstd = srstd;
#pragma unroll
    for (int i = 0; i < 3; i++) {
        int c = threadIdx.x + 256 * i;
        orow[c] = (v[i] - mean) * rstd * g[c] + bta[c];
    }
}

// ---------------- tensor-core GEMM: 64x128x32 tiles, tf32 mma ----------------
// SPLIT=1: fp32-accurate via hi/lo decomposition (3 mma per pair).
// Requires M%64==0, N%128==0, K%32==0.
#define ASZ_ (64 * 36)
#define BSZ_ (32 * 136)
template<int SPLIT, bool GELU, bool HASBIAS, bool HASRES>
__global__ void tgemm_kernel(const float* __restrict__ A, const float* __restrict__ Bm,
                             const float* __restrict__ bias, const float* __restrict__ res,
                             float* __restrict__ Co, int Nd, int Kd)
{
    extern __shared__ unsigned smu[];
    unsigned* AsH = smu;
    unsigned* AsL = AsH + ASZ_;                    // used iff SPLIT
    unsigned* BsH = AsH + ASZ_ * (1 + SPLIT);
    unsigned* BsL = BsH + BSZ_;                    // used iff SPLIT

    int tid = threadIdx.x;
    int lane = tid & 31, wid = tid >> 5;
    int wm = wid & 1, wn = wid >> 1;
    int g = lane >> 2, tg = lane & 3;
    int m0 = blockIdx.y * 64, n0 = blockIdx.x * 128;

    float acc[2][4][4];
#pragma unroll
    for (int i = 0; i < 2; i++)
#pragma unroll
        for (int j = 0; j < 4; j++)
#pragma unroll
            for (int q = 0; q < 4; q++) acc[i][j][q] = 0.f;

    int am = tid >> 3;              // 0..31 (and +32)
    int ak = (tid & 7) * 4;
    int bn = (tid & 31) * 4;        // B col within tile

    for (int k0 = 0; k0 < Kd; k0 += 32) {
        float4 a0 = *(const float4*)&A[(size_t)(m0 + am) * Kd + k0 + ak];
        float4 a1 = *(const float4*)&A[(size_t)(m0 + am + 32) * Kd + k0 + ak];
        float4 bv[4];
#pragma unroll
        for (int r = 0; r < 4; r++)
            bv[r] = *(const float4*)&Bm[(size_t)(k0 + r * 8 + wid) * Nd + n0 + bn];
        __syncthreads();
        {
            float av[2][4] = {{a0.x, a0.y, a0.z, a0.w}, {a1.x, a1.y, a1.z, a1.w}};
#pragma unroll
            for (int h = 0; h < 2; h++) {
                int base = (am + h * 32) * 36 + ak;
#pragma unroll
                for (int j = 0; j < 4; j++) {
                    unsigned hi = f2tf32(av[h][j]);
                    AsH[base + j] = hi;
                    if (SPLIT) AsL[base + j] = f2tf32(av[h][j] - __uint_as_float(hi));
                }
            }
#pragma unroll
            for (int r = 0; r < 4; r++) {
                int base = (r * 8 + wid) * 136 + bn;
                float bb[4] = {bv[r].x, bv[r].y, bv[r].z, bv[r].w};
#pragma unroll
                for (int j = 0; j < 4; j++) {
                    unsigned hi = f2tf32(bb[j]);
                    BsH[base + j] = hi;
                    if (SPLIT) BsL[base + j] = f2tf32(bb[j] - __uint_as_float(hi));
                }
            }
        }
        __syncthreads();

        int arow = wm * 32 + g;
#pragma unroll
        for (int ks = 0; ks < 4; ks++) {
            unsigned ah[2][4], al[2][4];
#pragma unroll
            for (int mf = 0; mf < 2; mf++) {
                int base = (arow + mf * 16) * 36 + ks * 8 + tg;
                ah[mf][0] = AsH[base];
                ah[mf][1] = AsH[base + 8 * 36];
                ah[mf][2] = AsH[base + 4];
                ah[mf][3] = AsH[base + 8 * 36 + 4];
                if (SPLIT) {
                    al[mf][0] = AsL[base];
                    al[mf][1] = AsL[base + 8 * 36];
                    al[mf][2] = AsL[base + 4];
                    al[mf][3] = AsL[base + 8 * 36 + 4];
                }
            }
            unsigned bh[4][2], bl[4][2];
#pragma unroll
            for (int nf = 0; nf < 4; nf++) {
                int bbase = (ks * 8 + tg) * 136 + wn * 32 + nf * 8 + g;
                bh[nf][0] = BsH[bbase];
                bh[nf][1] = BsH[bbase + 4 * 136];
                if (SPLIT) {
                    bl[nf][0] = BsL[bbase];
                    bl[nf][1] = BsL[bbase + 4 * 136];
                }
            }
#pragma unroll
            for (int mf = 0; mf < 2; mf++)
#pragma unroll
                for (int nf = 0; nf < 4; nf++) {
                    mma_tf32(acc[mf][nf], ah[mf], bh[nf]);
                    if (SPLIT) {
                        mma_tf32(acc[mf][nf], ah[mf], bl[nf]);
                        mma_tf32(acc[mf][nf], al[mf], bh[nf]);
                    }
                }
        }
    }

    // epilogue
#pragma unroll
    for (int mf = 0; mf < 2; mf++) {
        int row = m0 + wm * 32 + mf * 16 + g;
#pragma unroll
        for (int nf = 0; nf < 4; nf++) {
            int col = n0 + wn * 32 + nf * 8 + 2 * tg;
            float b0 = 0.f, b1 = 0.f;
            if (HASBIAS) { b0 = bias[col]; b1 = bias[col + 1]; }
#pragma unroll
            for (int half = 0; half < 2; half++) {
                int r = row + half * 8;
                float c0 = acc[mf][nf][half * 2 + 0] + b0;
                float c1 = acc[mf][nf][half * 2 + 1] + b1;
                if (GELU) {
                    c0 = 0.5f * c0 * (1.f + erff(c0 * 0.70710678118654752f));
                    c1 = 0.5f * c1 * (1.f + erff(c1 * 0.70710678118654752f));
                }
                size_t base = (size_t)r * Nd + col;
                if (HASRES) {
                    float2 rv = *(const float2*)&res[base];
                    c0 += rv.x; c1 += rv.y;
                }
                float2 ov; ov.x = c0; ov.y = c1;
                *(float2*)&Co[base] = ov;
            }
        }
    }
}

// ---------------- scores: S = (Q*scale) @ K^T, per (b,h), 64x64 tiles ----------------
__global__ void score_kernel(const float* __restrict__ qkv, float* __restrict__ attn)
{
    __shared__ float Qs[64][68];   // [d][m]
    __shared__ float Ks[64][68];   // [d][n]
    int bh = blockIdx.x;
    int b = bh / H_, hh = bh % H_;
    int m0 = blockIdx.y * 64, n0 = blockIdx.z * 64;
    int tid = threadIdx.x;

#pragma unroll
    for (int r = 0; r < 4; r++) {
        int i = tid + r * 256;
        int row = i >> 4, col4 = (i & 15) * 4;
        int mq = m0 + row, nk = n0 + row;
        float4 q = make_float4(0.f, 0.f, 0.f, 0.f);
        float4 k = make_float4(0.f, 0.f, 0.f, 0.f);
        if (mq < N_) q = *(const float4*)&qkv[(size_t)(b * N_ + mq) * 2304 + hh * 64 + col4];
        if (nk < N_) k = *(const float4*)&qkv[(size_t)(b * N_ + nk) * 2304 + 768 + hh * 64 + col4];
        Qs[col4 + 0][row] = q.x * 0.125f;
        Qs[col4 + 1][row] = q.y * 0.125f;
        Qs[col4 + 2][row] = q.z * 0.125f;
        Qs[col4 + 3][row] = q.w * 0.125f;
        Ks[col4 + 0][row] = k.x;
        Ks[col4 + 1][row] = k.y;
        Ks[col4 + 2][row] = k.z;
        Ks[col4 + 3][row] = k.w;
    }
    __syncthreads();

    int my = tid >> 4, nx = tid & 15;
    float acc[4][4];
#pragma unroll
    for (int i = 0; i < 4; i++)
#pragma unroll
        for (int j = 0; j < 4; j++) acc[i][j] = 0.f;
#pragma unroll
    for (int d = 0; d < 64; d++) {
        float4 a = *(const float4*)&Qs[d][my * 4];
        float4 bb = *(const float4*)&Ks[d][nx * 4];
        float av[4] = {a.x, a.y, a.z, a.w};
        float bv[4] = {bb.x, bb.y, bb.z, bb.w};
#pragma unroll
        for (int i = 0; i < 4; i++)
#pragma unroll
            for (int j = 0; j < 4; j++)
                acc[i][j] = fmaf(av[i], bv[j], acc[i][j]);
    }
#pragma unroll
    for (int i = 0; i < 4; i++) {
        int m = m0 + my * 4 + i;
        if (m >= N_) continue;
        float* arow = attn + ((size_t)bh * N_ + m) * N_;
#pragma unroll
        for (int j = 0; j < 4; j++) {
            int n = n0 + nx * 4 + j;
            if (n < N_) arow[n] = acc[i][j];
        }
    }
}

// ---------------- softmax: one warp per row ----------------
__global__ void softmax_kernel(float* __restrict__ attn)
{
    int row = blockIdx.x * 8 + (threadIdx.x >> 5);
    if (row >= B_ * H_ * N_) return;
    int lane = threadIdx.x & 31;
    float* arow = attn + (size_t)row * N_;
    float v[7];
    float mx = -1e30f;
#pragma unroll
    for (int c = 0; c < 7; c++) {
        int j = lane + c * 32;
        v[c] = (j < N_) ? arow[j] : -1e30f;
        mx = fmaxf(mx, v[c]);
    }
    for (int off = 16; off; off >>= 1) mx = fmaxf(mx, __shfl_xor_sync(0xffffffffu, mx, off));
    float sum = 0.f;
#pragma unroll
    for (int c = 0; c < 7; c++) { float e = expf(v[c] - mx); v[c] = e; sum += e; }
    for (int off = 16; off; off >>= 1) sum += __shfl_xor_sync(0xffffffffu, sum, off);
    float inv = 1.f / sum;
#pragma unroll
    for (int c = 0; c < 7; c++) {
        int j = lane + c * 32;
        if (j < N_) arow[j] = v[c] * inv;
    }
}

// ---------------- AV: O = attn @ V, per (b,h), 64-query tiles, 4x4 micro ----------------
__global__ void av_kernel(const float* __restrict__ qkv, const float* __restrict__ attn,
                          float* __restrict__ ao)
{
    __shared__ float As[32][68];   // [kk][m]
    __shared__ float Vs[32][68];   // [kk][d]
    int bh = blockIdx.x;
    int b = bh / H_, hh = bh % H_;
    int m0 = blockIdx.y * 64;
    int tid = threadIdx.x;
    int my = tid >> 4, nx = tid & 15;

    float acc[4][4];
#pragma unroll
    for (int i = 0; i < 4; i++)
#pragma unroll
        for (int j = 0; j < 4; j++) acc[i][j] = 0.f;

    for (int k0 = 0; k0 < N_; k0 += 32) {
#pragma unroll
        for (int r = 0; r < 8; r++) {
            int i = tid + r * 256;
            int kk = i & 31, mr = i >> 5;
            int m = m0 + mr, kj = k0 + kk;
            As[kk][mr] = (m < N_ && kj < N_) ? attn[((size_t)bh * N_ + m) * N_ + kj] : 0.f;
        }
#pragma unroll
        for (int r = 0; r < 8; r++) {
            int i = tid + r * 256;
            int d = i & 63, kk = i >> 6;
            int kj = k0 + kk;
            Vs[kk][d] = (kj < N_) ? qkv[(size_t)(b * N_ + kj) * 2304 + 1536 + hh * 64 + d] : 0.f;
        }
        __syncthreads();
#pragma unroll
        for (int kk = 0; kk < 32; kk++) {
            float4 a = *(const float4*)&As[kk][my * 4];
            float4 v = *(const float4*)&Vs[kk][nx * 4];
            float av[4] = {a.x, a.y, a.z, a.w};
            float vv[4] = {v.x, v.y, v.z, v.w};
#pragma unroll
            for (int i = 0; i < 4; i++)
#pragma unroll
                for (int j = 0; j < 4; j++)
                    acc[i][j] = fmaf(av[i], vv[j], acc[i][j]);
        }
        __syncthreads();
    }
#pragma unroll
    for (int i = 0; i < 4; i++) {
        int m = m0 + my * 4 + i;
        if (m >= N_) continue;
#pragma unroll
        for (int j = 0; j < 4; j++)
            ao[(size_t)(b * N_ + m) * 768 + hh * 64 + nx * 4 + j] = acc[i][j];
    }
}

// ---------------- selection ----------------
__global__ void select_kernel(const float* __restrict__ attn, int* __restrict__ ik,
                              int* __restrict__ ie)
{
    __shared__ float diag[196];
    __shared__ int kept[196];
    int b = blockIdx.x, tid = threadIdx.x;
    if (tid < 196) {
        float s = 0.f;
        for (int hh = 0; hh < H_; hh++)
            s += attn[((size_t)(b * H_ + hh) * N_ + (tid + 1)) * N_ + (tid + 1)];
        diag[tid] = s;
    }
    __syncthreads();
    if (tid < 196) {
        float di = diag[tid];
        int rank = 0;
        for (int j = 0; j < 196; j++) {
            float dj = diag[j];
            rank += (dj > di) || (dj == di && j < tid);
        }
        kept[tid] = (rank < NKEPT_) ? 1 : 0;
    }
    __syncthreads();
    if (tid < 196) {
        int mine = kept[tid];
        int pos = 0;
        for (int j = 0; j < tid; j++) pos += (kept[j] == mine);
        if (mine) ik[b * K_ + 1 + pos] = tid + 1;
        else      ie[b * R_ + pos]     = tid + 1;
    }
    if (tid == 0) ik[b * K_] = 0;
}

// ---------------- propagation ----------------
__global__ void propagate_kernel(const float* __restrict__ attn, const float* __restrict__ x1,
                                 const int* __restrict__ ikg, const int* __restrict__ ieg,
                                 float* __restrict__ x2)
{
    extern __shared__ float sm[];
    float* ws = sm;                 // K_*R_
    float* xe = sm + K_ * R_;       // R_*64
    __shared__ int ik[K_], ie[R_];
    __shared__ int cnt;
    int bh = blockIdx.x;
    int b = bh / H_, hh = bh % H_;
    int tid = threadIdx.x;
    if (tid < K_) ik[tid] = ikg[b * K_ + tid];
    if (tid < R_) ie[tid] = ieg[b * R_ + tid];
    __syncthreads();
    const float* ablk = attn + (size_t)bh * N_ * N_;
    for (int idx = tid; idx < K_ * R_; idx += 256) {
        int k = idx / R_, e = idx - k * R_;
        ws[idx] = ablk[(size_t)ik[k] * N_ + ie[e]];
    }
    for (int idx = tid; idx < R_ * 64; idx += 256) {
        int e = idx >> 6, d = idx & 63;
        xe[idx] = x1[(size_t)(b * N_ + ie[e]) * 768 + hh * 64 + d];
    }
    __syncthreads();

    unsigned lo = 0u, hi = 0x7f7fffffu;
    while (lo < hi) {
        unsigned mid = lo + ((hi - lo + 1) >> 1);
        if (tid == 0) cnt = 0;
        __syncthreads();
        int local = 0;
        for (int i = tid; i < K_ * R_; i += 256)
            local += (__float_as_uint(ws[i]) >= mid);
        for (int off = 16; off; off >>= 1) local += __shfl_xor_sync(0xffffffffu, local, off);
        if ((tid & 31) == 0) atomicAdd(&cnt, local);
        __syncthreads();
        int c = cnt;
        __syncthreads();
        if (c >= THRK_) lo = mid; else hi = mid - 1;
    }
    float thr = __uint_as_float(lo);

    for (int p = tid; p < K_ * 64; p += 256) {
        int k = p >> 6, d = p & 63;
        const float* wr = ws + k * R_;
        float acc = 0.f;
#pragma unroll 2
        for (int e = 0; e < R_; e++) {
            float wv = wr[e];
            wv = (wv >= thr) ? wv : 0.f;
            acc = fmaf(wv, xe[e * 64 + d], acc);
        }
        x2[(size_t)(b * K_ + k) * 768 + hh * 64 + d] =
            x1[(size_t)(b * N_ + ik[k]) * 768 + hh * 64 + d] + ALPHA_ * acc;
    }
}

// ---------------- host ----------------
extern "C" void kernel_launch(void* const* d_in, const int* in_sizes, int n_in,
                              void* d_out, int out_size)
{
    const float* x     = (const float*)d_in[0];
    const float* n1g   = (const float*)d_in[1];
    const float* n1b   = (const float*)d_in[2];
    const float* qkvw  = (const float*)d_in[3];
    const float* projw = (const float*)d_in[4];
    const float* projb = (const float*)d_in[5];
    const float* n2g   = (const float*)d_in[6];
    const float* n2b   = (const float*)d_in[7];
    const float* fc1w  = (const float*)d_in[8];
    const float* fc1b  = (const float*)d_in[9];
    const float* fc2w  = (const float*)d_in[10];
    const float* fc2b  = (const float*)d_in[11];
    float* out = (float*)d_out;

    float *h, *qkv, *attn, *ao, *x1, *x2, *h2, *mlp;
    int *ik, *ie;
    cudaGetSymbolAddress((void**)&h,    g_h);
    cudaGetSymbolAddress((void**)&qkv,  g_qkv);
    cudaGetSymbolAddress((void**)&attn, g_attn);
    cudaGetSymbolAddress((void**)&ao,   g_ao);
    cudaGetSymbolAddress((void**)&x1,   g_x1);
    cudaGetSymbolAddress((void**)&x2,   g_x2);
    cudaGetSymbolAddress((void**)&h2,   g_h2);
    cudaGetSymbolAddress((void**)&mlp,  g_mlp);
    cudaGetSymbolAddress((void**)&ik,   g_ik);
    cudaGetSymbolAddress((void**)&ie,   g_ie);

    const int PROP_SMEM = (K_ * R_ + R_ * 64) * 4;
    cudaFuncSetAttribute(propagate_kernel, cudaFuncAttributeMaxDynamicSharedMemorySize, PROP_SMEM);
    const int SMEM_SPLIT = (ASZ_ + BSZ_) * 2 * 4;   // 53248
    const int SMEM_PLAIN = (ASZ_ + BSZ_) * 4;       // 26624
    cudaFuncSetAttribute(tgemm_kernel<1, false, false, false>,
                         cudaFuncAttributeMaxDynamicSharedMemorySize, SMEM_SPLIT);
    cudaFuncSetAttribute(tgemm_kernel<0, false, true, true>,
                         cudaFuncAttributeMaxDynamicSharedMemorySize, SMEM_PLAIN);
    cudaFuncSetAttribute(tgemm_kernel<0, true, true, false>,
                         cudaFuncAttributeMaxDynamicSharedMemorySize, SMEM_PLAIN);

    // 1. LN1
    ln_kernel<<<B_ * N_, 256>>>(x, n1g, n1b, h);
    // 2. QKV GEMM (split-tf32: fp32-accurate -> selection ranks safe)
    tgemm_kernel<1, false, false, false><<<dim3(2304 / 128, 12608 / 64), 256, SMEM_SPLIT>>>(
        h, qkvw, nullptr, nullptr, qkv, 3 * C_, C_);
    // 3. scores
    score_kernel<<<dim3(B_ * H_, 4, 4), 256>>>(qkv, attn);
    // 4. softmax
    softmax_kernel<<<(B_ * H_ * N_ + 7) / 8, 256>>>(attn);
    // 5. attn @ V
    av_kernel<<<dim3(B_ * H_, 4), 256>>>(qkv, attn, ao);
    // 6. proj + bias + residual (plain tf32)
    tgemm_kernel<0, false, true, true><<<dim3(768 / 128, 12608 / 64), 256, SMEM_PLAIN>>>(
        ao, projw, projb, x, x1, C_, C_);
    // 7. selection
    select_kernel<<<B_, 256>>>(attn, ik, ie);
    // 8. propagation
    propagate_kernel<<<B_ * H_, 256, PROP_SMEM>>>(attn, x1, ik, ie, x2);
    // 9. LN2
    ln_kernel<<<B_ * K_, 256>>>(x2, n2g, n2b, h2);
    // 10. fc1 + gelu (plain tf32)
    tgemm_kernel<0, true, true, false><<<dim3(3072 / 128, 6336 / 64), 256, SMEM_PLAIN>>>(
        h2, fc1w, fc1b, nullptr, mlp, 4 * C_, C_);
    // 11. fc2 + residual -> out (plain tf32)
    tgemm_kernel<0, false, true, true><<<dim3(768 / 128, 6336 / 64), 256, SMEM_PLAIN>>>(
        mlp, fc2w, fc2b, x2, out, C_, 4 * C_);
}

// round 4
// speedup vs baseline: 2.6528x; 1.0244x over previous
#include <cuda_runtime.h>
#include <math.h>

#define B_   64
#define N_   197
#define C_   768
#define H_   12
#define DH_  64
#define R_   98
#define K_   99
#define NKEPT_ 98
#define THRK_ 1941
#define ALPHA_ 0.1f
#define EPS_ 1e-5f

// ---------------- scratch ----------------
__device__ float    g_qkv [(size_t)B_*N_*3*C_];
__device__ float    g_attn[(size_t)B_*H_*N_*N_];
__device__ float    g_x1  [(size_t)B_*N_*C_];
__device__ float    g_x2  [(size_t)B_*K_*C_];
__device__ int      g_ik  [B_*K_];
__device__ int      g_ie  [B_*R_];
// tf32 pre-converted operands
__device__ unsigned g_hh  [(size_t)B_*N_*C_];     // LN1 out hi
__device__ unsigned g_hl  [(size_t)B_*N_*C_];     // LN1 out lo
__device__ unsigned g_wqkvh[(size_t)C_*3*C_];
__device__ unsigned g_wqkvl[(size_t)C_*3*C_];
__device__ unsigned g_wprojh[(size_t)C_*C_];
__device__ unsigned g_wfc1h[(size_t)C_*4*C_];
__device__ unsigned g_wfc2h[(size_t)4*C_*C_];
__device__ unsigned g_aoh [(size_t)B_*N_*C_];     // attention out, tf32
__device__ unsigned g_h2h [(size_t)B_*K_*C_];     // LN2 out hi
__device__ unsigned g_mlph[(size_t)B_*K_*4*C_];   // fc1 out, tf32

// ---------------- helpers ----------------
__device__ __forceinline__ unsigned f2tf32(float x) {
    unsigned r;
    asm("cvt.rna.tf32.f32 %0, %1;" : "=r"(r) : "f"(x));
    return r;
}
__device__ __forceinline__ void mma_tf32(float c[4], const unsigned a[4], const unsigned b[2]) {
    asm volatile(
        "mma.sync.aligned.m16n8k8.row.col.f32.tf32.tf32.f32 "
        "{%0,%1,%2,%3},{%4,%5,%6,%7},{%8,%9},{%0,%1,%2,%3};"
        : "+f"(c[0]), "+f"(c[1]), "+f"(c[2]), "+f"(c[3])
        : "r"(a[0]), "r"(a[1]), "r"(a[2]), "r"(a[3]), "r"(b[0]), "r"(b[1]));
}

// ---------------- weight pre-conversion (hi, optional lo) ----------------
template<int WLO>
__global__ void cvtw_kernel(const float* __restrict__ s, unsigned* __restrict__ hi,
                            unsigned* __restrict__ lo, int n)
{
    int i = (blockIdx.x * 256 + threadIdx.x) * 4;
    if (i >= n) return;
    float4 v = *(const float4*)&s[i];
    uint4 h;
    h.x = f2tf32(v.x); h.y = f2tf32(v.y); h.z = f2tf32(v.z); h.w = f2tf32(v.w);
    *(uint4*)&hi[i] = h;
    if (WLO) {
        uint4 l;
        l.x = f2tf32(v.x - __uint_as_float(h.x));
        l.y = f2tf32(v.y - __uint_as_float(h.y));
        l.z = f2tf32(v.z - __uint_as_float(h.z));
        l.w = f2tf32(v.w - __uint_as_float(h.w));
        *(uint4*)&lo[i] = l;
    }
}

// ---------------- LayerNorm -> tf32 hi(/lo) ----------------
template<int WLO>
__global__ void ln_tf32_kernel(const float* __restrict__ x, const float* __restrict__ g,
                               const float* __restrict__ bta,
                               unsigned* __restrict__ hi, unsigned* __restrict__ lo)
{
    int row = blockIdx.x;
    const float* xr = x + (size_t)row * C_;
    float v[3]; float s = 0.f, ss = 0.f;
#pragma unroll
    for (int i = 0; i < 3; i++) {
        v[i] = xr[threadIdx.x + 256 * i];
        s += v[i]; ss = fmaf(v[i], v[i], ss);
    }
    for (int off = 16; off; off >>= 1) {
        s  += __shfl_xor_sync(0xffffffffu, s, off);
        ss += __shfl_xor_sync(0xffffffffu, ss, off);
    }
    __shared__ float rs[8], rss[8];
    __shared__ float smean, srstd;
    int w = threadIdx.x >> 5;
    if ((threadIdx.x & 31) == 0) { rs[w] = s; rss[w] = ss; }
    __syncthreads();
    if (threadIdx.x == 0) {
        float S = 0.f, SS = 0.f;
        for (int i = 0; i < 8; i++) { S += rs[i]; SS += rss[i]; }
        float mean = S * (1.f / C_);
        float var = SS * (1.f / C_) - mean * mean;
        smean = mean; srstd = rsqrtf(var + EPS_);
    }
    __syncthreads();
    float mean = smean, rstd = srstd;
#pragma unroll
    for (int i = 0; i < 3; i++) {
        int c = threadIdx.x + 256 * i;
        float val = (v[i] - mean) * rstd * g[c] + bta[c];
        unsigned hv = f2tf32(val);
        hi[(size_t)row * C_ + c] = hv;
        if (WLO) lo[(size_t)row * C_ + c] = f2tf32(val - __uint_as_float(hv));
    }
}

// ---------------- tensor-core GEMM: 64x128x32 tiles, pre-converted tf32 ----------------
#define ASZ_ (64 * 36)
#define BSZ_ (32 * 136)
template<int SPLIT, bool GELU, bool HASBIAS, bool HASRES, bool OUTU>
__global__ void tgemm_kernel(const unsigned* __restrict__ Ah, const unsigned* __restrict__ Al,
                             const unsigned* __restrict__ Bh, const unsigned* __restrict__ Bl,
                             const float* __restrict__ bias, const float* __restrict__ res,
                             float* __restrict__ Cf, unsigned* __restrict__ Cu,
                             int Nd, int Kd)
{
    extern __shared__ unsigned smu[];
    unsigned* AsH = smu;
    unsigned* AsL = AsH + ASZ_;
    unsigned* BsH = AsH + ASZ_ * (1 + SPLIT);
    unsigned* BsL = BsH + BSZ_;

    int tid = threadIdx.x;
    int lane = tid & 31, wid = tid >> 5;
    int wm = wid & 1, wn = wid >> 1;
    int g = lane >> 2, tg = lane & 3;
    int m0 = blockIdx.y * 64, n0 = blockIdx.x * 128;

    float acc[2][4][4];
#pragma unroll
    for (int i = 0; i < 2; i++)
#pragma unroll
        for (int j = 0; j < 4; j++)
#pragma unroll
            for (int q = 0; q < 4; q++) acc[i][j][q] = 0.f;

    int am = tid >> 3;
    int ak = (tid & 7) * 4;
    int bn = (tid & 31) * 4;

    for (int k0 = 0; k0 < Kd; k0 += 32) {
        uint4 a0h = *(const uint4*)&Ah[(size_t)(m0 + am) * Kd + k0 + ak];
        uint4 a1h = *(const uint4*)&Ah[(size_t)(m0 + am + 32) * Kd + k0 + ak];
        uint4 a0l, a1l;
        if (SPLIT) {
            a0l = *(const uint4*)&Al[(size_t)(m0 + am) * Kd + k0 + ak];
            a1l = *(const uint4*)&Al[(size_t)(m0 + am + 32) * Kd + k0 + ak];
        }
        uint4 bvh[4], bvl[4];
#pragma unroll
        for (int r = 0; r < 4; r++) {
            bvh[r] = *(const uint4*)&Bh[(size_t)(k0 + r * 8 + wid) * Nd + n0 + bn];
            if (SPLIT) bvl[r] = *(const uint4*)&Bl[(size_t)(k0 + r * 8 + wid) * Nd + n0 + bn];
        }
        __syncthreads();
        *(uint4*)&AsH[am * 36 + ak] = a0h;
        *(uint4*)&AsH[(am + 32) * 36 + ak] = a1h;
        if (SPLIT) {
            *(uint4*)&AsL[am * 36 + ak] = a0l;
            *(uint4*)&AsL[(am + 32) * 36 + ak] = a1l;
        }
#pragma unroll
        for (int r = 0; r < 4; r++) {
            *(uint4*)&BsH[(r * 8 + wid) * 136 + bn] = bvh[r];
            if (SPLIT) *(uint4*)&BsL[(r * 8 + wid) * 136 + bn] = bvl[r];
        }
        __syncthreads();

        int arow = wm * 32 + g;
#pragma unroll
        for (int ks = 0; ks < 4; ks++) {
            unsigned ah[2][4], al[2][4];
#pragma unroll
            for (int mf = 0; mf < 2; mf++) {
                int base = (arow + mf * 16) * 36 + ks * 8 + tg;
                ah[mf][0] = AsH[base];
                ah[mf][1] = AsH[base + 8 * 36];
                ah[mf][2] = AsH[base + 4];
                ah[mf][3] = AsH[base + 8 * 36 + 4];
                if (SPLIT) {
                    al[mf][0] = AsL[base];
                    al[mf][1] = AsL[base + 8 * 36];
                    al[mf][2] = AsL[base + 4];
                    al[mf][3] = AsL[base + 8 * 36 + 4];
                }
            }
            unsigned bh[4][2], bl[4][2];
#pragma unroll
            for (int nf = 0; nf < 4; nf++) {
                int bbase = (ks * 8 + tg) * 136 + wn * 32 + nf * 8 + g;
                bh[nf][0] = BsH[bbase];
                bh[nf][1] = BsH[bbase + 4 * 136];
                if (SPLIT) {
                    bl[nf][0] = BsL[bbase];
                    bl[nf][1] = BsL[bbase + 4 * 136];
                }
            }
#pragma unroll
            for (int mf = 0; mf < 2; mf++)
#pragma unroll
                for (int nf = 0; nf < 4; nf++) {
                    mma_tf32(acc[mf][nf], ah[mf], bh[nf]);
                    if (SPLIT) {
                        mma_tf32(acc[mf][nf], ah[mf], bl[nf]);
                        mma_tf32(acc[mf][nf], al[mf], bh[nf]);
                    }
                }
        }
    }

    // epilogue
#pragma unroll
    for (int mf = 0; mf < 2; mf++) {
        int row = m0 + wm * 32 + mf * 16 + g;
#pragma unroll
        for (int nf = 0; nf < 4; nf++) {
            int col = n0 + wn * 32 + nf * 8 + 2 * tg;
            float b0 = 0.f, b1 = 0.f;
            if (HASBIAS) { b0 = bias[col]; b1 = bias[col + 1]; }
#pragma unroll
            for (int half = 0; half < 2; half++) {
                int r = row + half * 8;
                float c0 = acc[mf][nf][half * 2 + 0] + b0;
                float c1 = acc[mf][nf][half * 2 + 1] + b1;
                if (GELU) {
                    c0 = 0.5f * c0 * (1.f + erff(c0 * 0.70710678118654752f));
                    c1 = 0.5f * c1 * (1.f + erff(c1 * 0.70710678118654752f));
                }
                size_t base = (size_t)r * Nd + col;
                if (HASRES) {
                    float2 rv = *(const float2*)&res[base];
                    c0 += rv.x; c1 += rv.y;
                }
                if (OUTU) {
                    uint2 ov; ov.x = f2tf32(c0); ov.y = f2tf32(c1);
                    *(uint2*)&Cu[base] = ov;
                } else {
                    float2 ov; ov.x = c0; ov.y = c1;
                    *(float2*)&Cf[base] = ov;
                }
            }
        }
    }
}

// ---------------- scores: S = (Q*scale) @ K^T (fp32, rank-critical) ----------------
__global__ void score_kernel(const float* __restrict__ qkv, float* __restrict__ attn)
{
    __shared__ float Qs[64][68];
    __shared__ float Ks[64][68];
    int bh = blockIdx.x;
    int b = bh / H_, hh = bh % H_;
    int m0 = blockIdx.y * 64, n0 = blockIdx.z * 64;
    int tid = threadIdx.x;

#pragma unroll
    for (int r = 0; r < 4; r++) {
        int i = tid + r * 256;
        int row = i >> 4, col4 = (i & 15) * 4;
        int mq = m0 + row, nk = n0 + row;
        float4 q = make_float4(0.f, 0.f, 0.f, 0.f);
        float4 k = make_float4(0.f, 0.f, 0.f, 0.f);
        if (mq < N_) q = *(const float4*)&qkv[(size_t)(b * N_ + mq) * 2304 + hh * 64 + col4];
        if (nk < N_) k = *(const float4*)&qkv[(size_t)(b * N_ + nk) * 2304 + 768 + hh * 64 + col4];
        Qs[col4 + 0][row] = q.x * 0.125f;
        Qs[col4 + 1][row] = q.y * 0.125f;
        Qs[col4 + 2][row] = q.z * 0.125f;
        Qs[col4 + 3][row] = q.w * 0.125f;
        Ks[col4 + 0][row] = k.x;
        Ks[col4 + 1][row] = k.y;
        Ks[col4 + 2][row] = k.z;
        Ks[col4 + 3][row] = k.w;
    }
    __syncthreads();

    int my = tid >> 4, nx = tid & 15;
    float acc[4][4];
#pragma unroll
    for (int i = 0; i < 4; i++)
#pragma unroll
        for (int j = 0; j < 4; j++) acc[i][j] = 0.f;
#pragma unroll
    for (int d = 0; d < 64; d++) {
        float4 a = *(const float4*)&Qs[d][my * 4];
        float4 bb = *(const float4*)&Ks[d][nx * 4];
        float av[4] = {a.x, a.y, a.z, a.w};
        float bv[4] = {bb.x, bb.y, bb.z, bb.w};
#pragma unroll
        for (int i = 0; i < 4; i++)
#pragma unroll
            for (int j = 0; j < 4; j++)
                acc[i][j] = fmaf(av[i], bv[j], acc[i][j]);
    }
#pragma unroll
    for (int i = 0; i < 4; i++) {
        int m = m0 + my * 4 + i;
        if (m >= N_) continue;
        float* arow = attn + ((size_t)bh * N_ + m) * N_;
#pragma unroll
        for (int j = 0; j < 4; j++) {
            int n = n0 + nx * 4 + j;
            if (n < N_) arow[n] = acc[i][j];
        }
    }
}

// ---------------- softmax ----------------
__global__ void softmax_kernel(float* __restrict__ attn)
{
    int row = blockIdx.x * 8 + (threadIdx.x >> 5);
    if (row >= B_ * H_ * N_) return;
    int lane = threadIdx.x & 31;
    float* arow = attn + (size_t)row * N_;
    float v[7];
    float mx = -1e30f;
#pragma unroll
    for (int c = 0; c < 7; c++) {
        int j = lane + c * 32;
        v[c] = (j < N_) ? arow[j] : -1e30f;
        mx = fmaxf(mx, v[c]);
    }
    for (int off = 16; off; off >>= 1) mx = fmaxf(mx, __shfl_xor_sync(0xffffffffu, mx, off));
    float sum = 0.f;
#pragma unroll
    for (int c = 0; c < 7; c++) { float e = expf(v[c] - mx); v[c] = e; sum += e; }
    for (int off = 16; off; off >>= 1) sum += __shfl_xor_sync(0xffffffffu, sum, off);
    float inv = 1.f / sum;
#pragma unroll
    for (int c = 0; c < 7; c++) {
        int j = lane + c * 32;
        if (j < N_) arow[j] = v[c] * inv;
    }
}

// ---------------- AV: O = attn @ V -> tf32 ao ----------------
__global__ void av_kernel(const float* __restrict__ qkv, const float* __restrict__ attn,
                          unsigned* __restrict__ aoh)
{
    __shared__ float As[32][68];
    __shared__ float Vs[32][68];
    int bh = blockIdx.x;
    int b = bh / H_, hh = bh % H_;
    int m0 = blockIdx.y * 64;
    int tid = threadIdx.x;
    int my = tid >> 4, nx = tid & 15;

    float acc[4][4];
#pragma unroll
    for (int i = 0; i < 4; i++)
#pragma unroll
        for (int j = 0; j < 4; j++) acc[i][j] = 0.f;

    for (int k0 = 0; k0 < N_; k0 += 32) {
#pragma unroll
        for (int r = 0; r < 8; r++) {
            int i = tid + r * 256;
            int kk = i & 31, mr = i >> 5;
            int m = m0 + mr, kj = k0 + kk;
            As[kk][mr] = (m < N_ && kj < N_) ? attn[((size_t)bh * N_ + m) * N_ + kj] : 0.f;
        }
#pragma unroll
        for (int r = 0; r < 8; r++) {
            int i = tid + r * 256;
            int d = i & 63, kk = i >> 6;
            int kj = k0 + kk;
            Vs[kk][d] = (kj < N_) ? qkv[(size_t)(b * N_ + kj) * 2304 + 1536 + hh * 64 + d] : 0.f;
        }
        __syncthreads();
#pragma unroll
        for (int kk = 0; kk < 32; kk++) {
            float4 a = *(const float4*)&As[kk][my * 4];
            float4 v = *(const float4*)&Vs[kk][nx * 4];
            float av[4] = {a.x, a.y, a.z, a.w};
            float vv[4] = {v.x, v.y, v.z, v.w};
#pragma unroll
            for (int i = 0; i < 4; i++)
#pragma unroll
                for (int j = 0; j < 4; j++)
                    acc[i][j] = fmaf(av[i], vv[j], acc[i][j]);
        }
        __syncthreads();
    }
#pragma unroll
    for (int i = 0; i < 4; i++) {
        int m = m0 + my * 4 + i;
        if (m >= N_) continue;
#pragma unroll
        for (int j = 0; j < 4; j++)
            aoh[(size_t)(b * N_ + m) * 768 + hh * 64 + nx * 4 + j] = f2tf32(acc[i][j]);
    }
}

// ---------------- selection ----------------
__global__ void select_kernel(const float* __restrict__ attn, int* __restrict__ ik,
                              int* __restrict__ ie)
{
    __shared__ float diag[196];
    __shared__ int kept[196];
    int b = blockIdx.x, tid = threadIdx.x;
    if (tid < 196) {
        float s = 0.f;
        for (int hh = 0; hh < H_; hh++)
            s += attn[((size_t)(b * H_ + hh) * N_ + (tid + 1)) * N_ + (tid + 1)];
        diag[tid] = s;
    }
    __syncthreads();
    if (tid < 196) {
        float di = diag[tid];
        int rank = 0;
        for (int j = 0; j < 196; j++) {
            float dj = diag[j];
            rank += (dj > di) || (dj == di && j < tid);
        }
        kept[tid] = (rank < NKEPT_) ? 1 : 0;
    }
    __syncthreads();
    if (tid < 196) {
        int mine = kept[tid];
        int pos = 0;
        for (int j = 0; j < tid; j++) pos += (kept[j] == mine);
        if (mine) ik[b * K_ + 1 + pos] = tid + 1;
        else      ie[b * R_ + pos]     = tid + 1;
    }
    if (tid == 0) ik[b * K_] = 0;
}

// ---------------- propagation ----------------
__global__ void propagate_kernel(const float* __restrict__ attn, const float* __restrict__ x1,
                                 const int* __restrict__ ikg, const int* __restrict__ ieg,
                                 float* __restrict__ x2)
{
    extern __shared__ float sm[];
    float* ws = sm;
    float* xe = sm + K_ * R_;
    __shared__ int ik[K_], ie[R_];
    __shared__ int cnt;
    int bh = blockIdx.x;
    int b = bh / H_, hh = bh % H_;
    int tid = threadIdx.x;
    if (tid < K_) ik[tid] = ikg[b * K_ + tid];
    if (tid < R_) ie[tid] = ieg[b * R_ + tid];
    __syncthreads();
    const float* ablk = attn + (size_t)bh * N_ * N_;
    for (int idx = tid; idx < K_ * R_; idx += 256) {
        int k = idx / R_, e = idx - k * R_;
        ws[idx] = ablk[(size_t)ik[k] * N_ + ie[e]];
    }
    for (int idx = tid; idx < R_ * 64; idx += 256) {
        int e = idx >> 6, d = idx & 63;
        xe[idx] = x1[(size_t)(b * N_ + ie[e]) * 768 + hh * 64 + d];
    }
    __syncthreads();

    unsigned lo = 0u, hi = 0x7f7fffffu;
    while (lo < hi) {
        unsigned mid = lo + ((hi - lo + 1) >> 1);
        if (tid == 0) cnt = 0;
        __syncthreads();
        int local = 0;
        for (int i = tid; i < K_ * R_; i += 256)
            local += (__float_as_uint(ws[i]) >= mid);
        for (int off = 16; off; off >>= 1) local += __shfl_xor_sync(0xffffffffu, local, off);
        if ((tid & 31) == 0) atomicAdd(&cnt, local);
        __syncthreads();
        int c = cnt;
        __syncthreads();
        if (c >= THRK_) lo = mid; else hi = mid - 1;
    }
    float thr = __uint_as_float(lo);

    for (int p = tid; p < K_ * 64; p += 256) {
        int k = p >> 6, d = p & 63;
        const float* wr = ws + k * R_;
        float acc = 0.f;
#pragma unroll 2
        for (int e = 0; e < R_; e++) {
            float wv = wr[e];
            wv = (wv >= thr) ? wv : 0.f;
            acc = fmaf(wv, xe[e * 64 + d], acc);
        }
        x2[(size_t)(b * K_ + k) * 768 + hh * 64 + d] =
            x1[(size_t)(b * N_ + ik[k]) * 768 + hh * 64 + d] + ALPHA_ * acc;
    }
}

// ---------------- host ----------------
extern "C" void kernel_launch(void* const* d_in, const int* in_sizes, int n_in,
                              void* d_out, int out_size)
{
    const float* x     = (const float*)d_in[0];
    const float* n1g   = (const float*)d_in[1];
    const float* n1b   = (const float*)d_in[2];
    const float* qkvw  = (const float*)d_in[3];
    const float* projw = (const float*)d_in[4];
    const float* projb = (const float*)d_in[5];
    const float* n2g   = (const float*)d_in[6];
    const float* n2b   = (const float*)d_in[7];
    const float* fc1w  = (const float*)d_in[8];
    const float* fc1b  = (const float*)d_in[9];
    const float* fc2w  = (const float*)d_in[10];
    const float* fc2b  = (const float*)d_in[11];
    float* out = (float*)d_out;

    float *qkv, *attn, *x1, *x2;
    int *ik, *ie;
    unsigned *hh, *hl, *wqkvh, *wqkvl, *wprojh, *wfc1h, *wfc2h, *aoh, *h2h, *mlph;
    cudaGetSymbolAddress((void**)&qkv,  g_qkv);
    cudaGetSymbolAddress((void**)&attn, g_attn);
    cudaGetSymbolAddress((void**)&x1,   g_x1);
    cudaGetSymbolAddress((void**)&x2,   g_x2);
    cudaGetSymbolAddress((void**)&ik,   g_ik);
    cudaGetSymbolAddress((void**)&ie,   g_ie);
    cudaGetSymbolAddress((void**)&hh,   g_hh);
    cudaGetSymbolAddress((void**)&hl,   g_hl);
    cudaGetSymbolAddress((void**)&wqkvh, g_wqkvh);
    cudaGetSymbolAddress((void**)&wqkvl, g_wqkvl);
    cudaGetSymbolAddress((void**)&wprojh, g_wprojh);
    cudaGetSymbolAddress((void**)&wfc1h, g_wfc1h);
    cudaGetSymbolAddress((void**)&wfc2h, g_wfc2h);
    cudaGetSymbolAddress((void**)&aoh,  g_aoh);
    cudaGetSymbolAddress((void**)&h2h,  g_h2h);
    cudaGetSymbolAddress((void**)&mlph, g_mlph);

    const int PROP_SMEM = (K_ * R_ + R_ * 64) * 4;
    cudaFuncSetAttribute(propagate_kernel, cudaFuncAttributeMaxDynamicSharedMemorySize, PROP_SMEM);
    const int SMEM_SPLIT = (ASZ_ + BSZ_) * 2 * 4;
    const int SMEM_PLAIN = (ASZ_ + BSZ_) * 4;
    cudaFuncSetAttribute(tgemm_kernel<1, false, false, false, false>,
                         cudaFuncAttributeMaxDynamicSharedMemorySize, SMEM_SPLIT);
    cudaFuncSetAttribute(tgemm_kernel<0, false, false, false, false>,
                         cudaFuncAttributeMaxDynamicSharedMemorySize, SMEM_PLAIN);
    cudaFuncSetAttribute(tgemm_kernel<0, false, true, true, false>,
                         cudaFuncAttributeMaxDynamicSharedMemorySize, SMEM_PLAIN);
    cudaFuncSetAttribute(tgemm_kernel<0, true, true, false, true>,
                         cudaFuncAttributeMaxDynamicSharedMemorySize, SMEM_PLAIN);

    // 0. weight pre-conversion
    cvtw_kernel<1><<<(C_ * 3 * C_) / 1024, 256>>>(qkvw, wqkvh, wqkvl, C_ * 3 * C_);
    cvtw_kernel<0><<<(C_ * C_) / 1024, 256>>>(projw, wprojh, nullptr, C_ * C_);
    cvtw_kernel<0><<<(C_ * 4 * C_) / 1024, 256>>>(fc1w, wfc1h, nullptr, C_ * 4 * C_);
    cvtw_kernel<0><<<(4 * C_ * C_) / 1024, 256>>>(fc2w, wfc2h, nullptr, 4 * C_ * C_);

    // 1. LN1 -> tf32 hi/lo
    ln_tf32_kernel<1><<<B_ * N_, 256>>>(x, n1g, n1b, hh, hl);
    // 2a. QK part of QKV (split tf32, rank-critical): columns [0,1536)
    tgemm_kernel<1, false, false, false, false><<<dim3(12, 197), 256, SMEM_SPLIT>>>(
        hh, hl, wqkvh, wqkvl, nullptr, nullptr, qkv, nullptr, 3 * C_, C_);
    // 2b. V part (plain tf32): columns [1536,2304)
    tgemm_kernel<0, false, false, false, false><<<dim3(6, 197), 256, SMEM_PLAIN>>>(
        hh, nullptr, wqkvh + 1536, nullptr, nullptr, nullptr, qkv + 1536, nullptr, 3 * C_, C_);
    // 3. scores
    score_kernel<<<dim3(B_ * H_, 4, 4), 256>>>(qkv, attn);
    // 4. softmax
    softmax_kernel<<<(B_ * H_ * N_ + 7) / 8, 256>>>(attn);
    // 5. attn @ V -> tf32 ao
    av_kernel<<<dim3(B_ * H_, 4), 256>>>(qkv, attn, aoh);
    // 6. proj + bias + residual (plain tf32)
    tgemm_kernel<0, false, true, true, false><<<dim3(6, 197), 256, SMEM_PLAIN>>>(
        aoh, nullptr, wprojh, nullptr, projb, x, x1, nullptr, C_, C_);
    // 7. selection
    select_kernel<<<B_, 256>>>(attn, ik, ie);
    // 8. propagation
    propagate_kernel<<<B_ * H_, 256, PROP_SMEM>>>(attn, x1, ik, ie, x2);
    // 9. LN2 -> tf32 hi
    ln_tf32_kernel<0><<<B_ * K_, 256>>>(x2, n2g, n2b, h2h, nullptr);
    // 10. fc1 + gelu -> tf32 mlp
    tgemm_kernel<0, true, true, false, true><<<dim3(24, 99), 256, SMEM_PLAIN>>>(
        h2h, nullptr, wfc1h, nullptr, fc1b, nullptr, nullptr, mlph, 4 * C_, C_);
    // 11. fc2 + residual -> out
    tgemm_kernel<0, false, true, true, false><<<dim3(6, 99), 256, SMEM_PLAIN>>>(
        mlph, nullptr, wfc2h, nullptr, fc2b, x2, out, nullptr, C_, 4 * C_);
}

// round 5
// speedup vs baseline: 3.3692x; 1.2700x over previous
#include <cuda_runtime.h>
#include <cuda_fp16.h>
#include <math.h>

#define B_   64
#define N_   197
#define C_   768
#define H_   12
#define DH_  64
#define R_   98
#define K_   99
#define NKEPT_ 98
#define THRK_ 1941
#define ALPHA_ 0.1f
#define EPS_ 1e-5f

// ---------------- scratch ----------------
__device__ float    g_qkv [(size_t)B_*N_*3*C_];
__device__ float    g_attn[(size_t)B_*H_*N_*N_];
__device__ float    g_x1  [(size_t)B_*N_*C_];
__device__ float    g_x2  [(size_t)B_*K_*C_];
__device__ int      g_ik  [B_*K_];
__device__ int      g_ie  [B_*R_];
// packed fp16 operands (half2 along K)
__device__ unsigned g_hh  [(size_t)B_*N_*C_/2];      // LN1 out hi
__device__ unsigned g_hl  [(size_t)B_*N_*C_/2];      // LN1 out lo
__device__ unsigned g_wqkvh[(size_t)C_/2*3*C_];
__device__ unsigned g_wqkvl[(size_t)C_/2*3*C_];
__device__ unsigned g_wprojh[(size_t)C_/2*C_];
__device__ unsigned g_wfc1h[(size_t)C_/2*4*C_];
__device__ unsigned g_wfc2h[(size_t)4*C_/2*C_];
__device__ unsigned g_aoh [(size_t)B_*N_*C_/2];      // attention out
__device__ unsigned g_h2h [(size_t)B_*K_*C_/2];      // LN2 out
__device__ unsigned g_mlph[(size_t)B_*K_*4*C_/2];    // fc1 out

// ---------------- helpers ----------------
__device__ __forceinline__ unsigned packh2(float a, float b) {
    __half2 h = __floats2half2_rn(a, b);
    return *reinterpret_cast<unsigned*>(&h);
}
__device__ __forceinline__ void splith2(float a, float b, unsigned& hi, unsigned& lo) {
    __half ah = __float2half_rn(a), bh = __float2half_rn(b);
    __half2 h = __halves2half2(ah, bh);
    hi = *reinterpret_cast<unsigned*>(&h);
    lo = packh2(a - __half2float(ah), b - __half2float(bh));
}
__device__ __forceinline__ void mma_f16(float c[4], const unsigned a[4], const unsigned b[2]) {
    asm volatile(
        "mma.sync.aligned.m16n8k16.row.col.f32.f16.f16.f32 "
        "{%0,%1,%2,%3},{%4,%5,%6,%7},{%8,%9},{%0,%1,%2,%3};"
        : "+f"(c[0]), "+f"(c[1]), "+f"(c[2]), "+f"(c[3])
        : "r"(a[0]), "r"(a[1]), "r"(a[2]), "r"(a[3]), "r"(b[0]), "r"(b[1]));
}

// ---------------- weight pack: [K][N] fp32 -> [K/2][N] half2 (hi, opt lo) ----------------
template<int SPLIT>
__global__ void cvtw_pack(const float* __restrict__ w, unsigned* __restrict__ hi,
                          unsigned* __restrict__ lo, int Nd, int totalWords)
{
    int idx = blockIdx.x * 256 + threadIdx.x;
    if (idx >= totalWords) return;
    int kk = idx / Nd, n = idx - kk * Nd;
    float e = w[(size_t)(2 * kk) * Nd + n];
    float o = w[(size_t)(2 * kk + 1) * Nd + n];
    if (SPLIT) {
        unsigned h, l;
        splith2(e, o, h, l);
        hi[idx] = h; lo[idx] = l;
    } else {
        hi[idx] = packh2(e, o);
    }
}

// ---------------- LayerNorm -> packed fp16 hi(/lo) ----------------
template<int SPLIT>
__global__ void ln_pack_kernel(const float* __restrict__ x, const float* __restrict__ g,
                               const float* __restrict__ bta,
                               unsigned* __restrict__ hi, unsigned* __restrict__ lo)
{
    int row = blockIdx.x;
    const float2* xr = (const float2*)(x + (size_t)row * C_);
    int tid = threadIdx.x;
    float2 v1 = xr[tid];
    float2 v2 = make_float2(0.f, 0.f);
    if (tid < 128) v2 = xr[tid + 256];
    float s = v1.x + v1.y + v2.x + v2.y;
    float ss = v1.x * v1.x + v1.y * v1.y + v2.x * v2.x + v2.y * v2.y;
    for (int off = 16; off; off >>= 1) {
        s  += __shfl_xor_sync(0xffffffffu, s, off);
        ss += __shfl_xor_sync(0xffffffffu, ss, off);
    }
    __shared__ float rs[8], rss[8];
    __shared__ float smean, srstd;
    int w = tid >> 5;
    if ((tid & 31) == 0) { rs[w] = s; rss[w] = ss; }
    __syncthreads();
    if (tid == 0) {
        float S = 0.f, SS = 0.f;
        for (int i = 0; i < 8; i++) { S += rs[i]; SS += rss[i]; }
        float mean = S * (1.f / C_);
        float var = SS * (1.f / C_) - mean * mean;
        smean = mean; srstd = rsqrtf(var + EPS_);
    }
    __syncthreads();
    float mean = smean, rstd = srstd;
    size_t base = (size_t)row * (C_ / 2);
#pragma unroll
    for (int p = 0; p < 2; p++) {
        if (p == 1 && tid >= 128) break;
        int wi = tid + p * 256;
        float2 v = (p == 0) ? v1 : v2;
        int c = wi * 2;
        float a = (v.x - mean) * rstd * g[c] + bta[c];
        float b = (v.y - mean) * rstd * g[c + 1] + bta[c + 1];
        if (SPLIT) {
            unsigned h, l;
            splith2(a, b, h, l);
            hi[base + wi] = h; lo[base + wi] = l;
        } else {
            hi[base + wi] = packh2(a, b);
        }
    }
}

// ---------------- fp16 tensor GEMM: 64x128 tiles, k-step 32, m16n8k16 ----------------
// A packed [M][Kd/2], B packed [Kd/2][Nd]. SPLIT=1: hi/lo (3 mma). Out: float (ldc) or packed.
#define HA_W 20
#define HASZ (64 * HA_W)
#define HBSZ (16 * 132)
template<int SPLIT, bool GELU, bool HASBIAS, bool HASRES, bool OUTPACK>
__global__ void hgemm_kernel(const unsigned* __restrict__ Ah, const unsigned* __restrict__ Al,
                             const unsigned* __restrict__ Bh, const unsigned* __restrict__ Bl,
                             const float* __restrict__ bias, const float* __restrict__ res,
                             float* __restrict__ Cf, unsigned* __restrict__ Cu,
                             int Nd, int Kd, int ldc)
{
    extern __shared__ unsigned smu[];
    unsigned* AsH = smu;
    unsigned* AsL = AsH + HASZ;
    unsigned* BsH = AsH + HASZ * (1 + SPLIT);
    unsigned* BsL = BsH + HBSZ;

    int tid = threadIdx.x;
    int lane = tid & 31, wid = tid >> 5;
    int wm = wid & 1, wn = wid >> 1;
    int g = lane >> 2, tg = lane & 3;
    int m0 = blockIdx.y * 64, n0 = blockIdx.x * 128;
    int Kw = Kd / 2;

    float acc[2][4][4];
#pragma unroll
    for (int i = 0; i < 2; i++)
#pragma unroll
        for (int j = 0; j < 4; j++)
#pragma unroll
            for (int q = 0; q < 4; q++) acc[i][j][q] = 0.f;

    int am = tid >> 2;            // 0..63
    int aw = (tid & 3) * 4;       // word col
    int bkw = tid >> 5;           // 0..7 (and +8)
    int bn4 = (tid & 31) * 4;

    for (int k0w = 0; k0w < Kw; k0w += 16) {
        uint4 avh = *(const uint4*)&Ah[(size_t)(m0 + am) * Kw + k0w + aw];
        uint4 avl;
        if (SPLIT) avl = *(const uint4*)&Al[(size_t)(m0 + am) * Kw + k0w + aw];
        uint4 bvh0 = *(const uint4*)&Bh[(size_t)(k0w + bkw) * Nd + n0 + bn4];
        uint4 bvh1 = *(const uint4*)&Bh[(size_t)(k0w + bkw + 8) * Nd + n0 + bn4];
        uint4 bvl0, bvl1;
        if (SPLIT) {
            bvl0 = *(const uint4*)&Bl[(size_t)(k0w + bkw) * Nd + n0 + bn4];
            bvl1 = *(const uint4*)&Bl[(size_t)(k0w + bkw + 8) * Nd + n0 + bn4];
        }
        __syncthreads();
        *(uint4*)&AsH[am * HA_W + aw] = avh;
        if (SPLIT) *(uint4*)&AsL[am * HA_W + aw] = avl;
        *(uint4*)&BsH[bkw * 132 + bn4] = bvh0;
        *(uint4*)&BsH[(bkw + 8) * 132 + bn4] = bvh1;
        if (SPLIT) {
            *(uint4*)&BsL[bkw * 132 + bn4] = bvl0;
            *(uint4*)&BsL[(bkw + 8) * 132 + bn4] = bvl1;
        }
        __syncthreads();

        int arow = wm * 32 + g;
#pragma unroll
        for (int s = 0; s < 2; s++) {
            unsigned ah[2][4], al[2][4];
#pragma unroll
            for (int mf = 0; mf < 2; mf++) {
                int base = (arow + mf * 16) * HA_W + s * 8 + tg;
                ah[mf][0] = AsH[base];
                ah[mf][1] = AsH[base + 8 * HA_W];
                ah[mf][2] = AsH[base + 4];
                ah[mf][3] = AsH[base + 8 * HA_W + 4];
                if (SPLIT) {
                    al[mf][0] = AsL[base];
                    al[mf][1] = AsL[base + 8 * HA_W];
                    al[mf][2] = AsL[base + 4];
                    al[mf][3] = AsL[base + 8 * HA_W + 4];
                }
            }
            unsigned bh[4][2], bl[4][2];
#pragma unroll
            for (int nf = 0; nf < 4; nf++) {
                int n = wn * 32 + nf * 8 + g;
                bh[nf][0] = BsH[(s * 8 + tg) * 132 + n];
                bh[nf][1] = BsH[(s * 8 + tg + 4) * 132 + n];
                if (SPLIT) {
                    bl[nf][0] = BsL[(s * 8 + tg) * 132 + n];
                    bl[nf][1] = BsL[(s * 8 + tg + 4) * 132 + n];
                }
            }
#pragma unroll
            for (int mf = 0; mf < 2; mf++)
#pragma unroll
                for (int nf = 0; nf < 4; nf++) {
                    mma_f16(acc[mf][nf], ah[mf], bh[nf]);
                    if (SPLIT) {
                        mma_f16(acc[mf][nf], ah[mf], bl[nf]);
                        mma_f16(acc[mf][nf], al[mf], bh[nf]);
                    }
                }
        }
    }

    // epilogue
#pragma unroll
    for (int mf = 0; mf < 2; mf++) {
        int row = m0 + wm * 32 + mf * 16 + g;
#pragma unroll
        for (int nf = 0; nf < 4; nf++) {
            int col = n0 + wn * 32 + nf * 8 + 2 * tg;
            float b0 = 0.f, b1 = 0.f;
            if (HASBIAS) { b0 = bias[col]; b1 = bias[col + 1]; }
#pragma unroll
            for (int half = 0; half < 2; half++) {
                int r = row + half * 8;
                float c0 = acc[mf][nf][half * 2 + 0] + b0;
                float c1 = acc[mf][nf][half * 2 + 1] + b1;
                if (GELU) {
                    c0 = 0.5f * c0 * (1.f + erff(c0 * 0.70710678118654752f));
                    c1 = 0.5f * c1 * (1.f + erff(c1 * 0.70710678118654752f));
                }
                if (OUTPACK) {
                    Cu[(size_t)r * (Nd / 2) + col / 2] = packh2(c0, c1);
                } else {
                    size_t base = (size_t)r * ldc + col;
                    if (HASRES) {
                        float2 rv = *(const float2*)&res[base];
                        c0 += rv.x; c1 += rv.y;
                    }
                    float2 ov; ov.x = c0; ov.y = c1;
                    *(float2*)&Cf[base] = ov;
                }
            }
        }
    }
}

// ---------------- scores: S = (Q*scale) @ K^T (fp32, rank-critical) ----------------
__global__ void score_kernel(const float* __restrict__ qkv, float* __restrict__ attn)
{
    __shared__ float Qs[64][68];
    __shared__ float Ks[64][68];
    int bh = blockIdx.x;
    int b = bh / H_, hh = bh % H_;
    int m0 = blockIdx.y * 64, n0 = blockIdx.z * 64;
    int tid = threadIdx.x;

#pragma unroll
    for (int r = 0; r < 4; r++) {
        int i = tid + r * 256;
        int row = i >> 4, col4 = (i & 15) * 4;
        int mq = m0 + row, nk = n0 + row;
        float4 q = make_float4(0.f, 0.f, 0.f, 0.f);
        float4 k = make_float4(0.f, 0.f, 0.f, 0.f);
        if (mq < N_) q = *(const float4*)&qkv[(size_t)(b * N_ + mq) * 2304 + hh * 64 + col4];
        if (nk < N_) k = *(const float4*)&qkv[(size_t)(b * N_ + nk) * 2304 + 768 + hh * 64 + col4];
        Qs[col4 + 0][row] = q.x * 0.125f;
        Qs[col4 + 1][row] = q.y * 0.125f;
        Qs[col4 + 2][row] = q.z * 0.125f;
        Qs[col4 + 3][row] = q.w * 0.125f;
        Ks[col4 + 0][row] = k.x;
        Ks[col4 + 1][row] = k.y;
        Ks[col4 + 2][row] = k.z;
        Ks[col4 + 3][row] = k.w;
    }
    __syncthreads();

    int my = tid >> 4, nx = tid & 15;
    float acc[4][4];
#pragma unroll
    for (int i = 0; i < 4; i++)
#pragma unroll
        for (int j = 0; j < 4; j++) acc[i][j] = 0.f;
#pragma unroll
    for (int d = 0; d < 64; d++) {
        float4 a = *(const float4*)&Qs[d][my * 4];
        float4 bb = *(const float4*)&Ks[d][nx * 4];
        float av[4] = {a.x, a.y, a.z, a.w};
        float bv[4] = {bb.x, bb.y, bb.z, bb.w};
#pragma unroll
        for (int i = 0; i < 4; i++)
#pragma unroll
            for (int j = 0; j < 4; j++)
                acc[i][j] = fmaf(av[i], bv[j], acc[i][j]);
    }
#pragma unroll
    for (int i = 0; i < 4; i++) {
        int m = m0 + my * 4 + i;
        if (m >= N_) continue;
        float* arow = attn + ((size_t)bh * N_ + m) * N_;
#pragma unroll
        for (int j = 0; j < 4; j++) {
            int n = n0 + nx * 4 + j;
            if (n < N_) arow[n] = acc[i][j];
        }
    }
}

// ---------------- softmax ----------------
__global__ void softmax_kernel(float* __restrict__ attn)
{
    int row = blockIdx.x * 8 + (threadIdx.x >> 5);
    if (row >= B_ * H_ * N_) return;
    int lane = threadIdx.x & 31;
    float* arow = attn + (size_t)row * N_;
    float v[7];
    float mx = -1e30f;
#pragma unroll
    for (int c = 0; c < 7; c++) {
        int j = lane + c * 32;
        v[c] = (j < N_) ? arow[j] : -1e30f;
        mx = fmaxf(mx, v[c]);
    }
    for (int off = 16; off; off >>= 1) mx = fmaxf(mx, __shfl_xor_sync(0xffffffffu, mx, off));
    float sum = 0.f;
#pragma unroll
    for (int c = 0; c < 7; c++) { float e = expf(v[c] - mx); v[c] = e; sum += e; }
    for (int off = 16; off; off >>= 1) sum += __shfl_xor_sync(0xffffffffu, sum, off);
    float inv = 1.f / sum;
#pragma unroll
    for (int c = 0; c < 7; c++) {
        int j = lane + c * 32;
        if (j < N_) arow[j] = v[c] * inv;
    }
}

// ---------------- AV: O = attn @ V -> packed fp16 ao ----------------
__global__ void av_kernel(const float* __restrict__ qkv, const float* __restrict__ attn,
                          unsigned* __restrict__ aoh)
{
    __shared__ float As[32][68];
    __shared__ float Vs[32][68];
    int bh = blockIdx.x;
    int b = bh / H_, hh = bh % H_;
    int m0 = blockIdx.y * 64;
    int tid = threadIdx.x;
    int my = tid >> 4, nx = tid & 15;

    float acc[4][4];
#pragma unroll
    for (int i = 0; i < 4; i++)
#pragma unroll
        for (int j = 0; j < 4; j++) acc[i][j] = 0.f;

    for (int k0 = 0; k0 < N_; k0 += 32) {
#pragma unroll
        for (int r = 0; r < 8; r++) {
            int i = tid + r * 256;
            int kk = i & 31, mr = i >> 5;
            int m = m0 + mr, kj = k0 + kk;
            As[kk][mr] = (m < N_ && kj < N_) ? attn[((size_t)bh * N_ + m) * N_ + kj] : 0.f;
        }
#pragma unroll
        for (int r = 0; r < 8; r++) {
            int i = tid + r * 256;
            int d = i & 63, kk = i >> 6;
            int kj = k0 + kk;
            Vs[kk][d] = (kj < N_) ? qkv[(size_t)(b * N_ + kj) * 2304 + 1536 + hh * 64 + d] : 0.f;
        }
        __syncthreads();
#pragma unroll
        for (int kk = 0; kk < 32; kk++) {
            float4 a = *(const float4*)&As[kk][my * 4];
            float4 v = *(const float4*)&Vs[kk][nx * 4];
            float av[4] = {a.x, a.y, a.z, a.w};
            float vv[4] = {v.x, v.y, v.z, v.w};
#pragma unroll
            for (int i = 0; i < 4; i++)
#pragma unroll
                for (int j = 0; j < 4; j++)
                    acc[i][j] = fmaf(av[i], vv[j], acc[i][j]);
        }
        __syncthreads();
    }
#pragma unroll
    for (int i = 0; i < 4; i++) {
        int m = m0 + my * 4 + i;
        if (m >= N_) continue;
        size_t base = (size_t)(b * N_ + m) * 384 + hh * 32 + nx * 2;
        aoh[base]     = packh2(acc[i][0], acc[i][1]);
        aoh[base + 1] = packh2(acc[i][2], acc[i][3]);
    }
}

// ---------------- selection ----------------
__global__ void select_kernel(const float* __restrict__ attn, int* __restrict__ ik,
                              int* __restrict__ ie)
{
    __shared__ float diag[196];
    __shared__ int kept[196];
    int b = blockIdx.x, tid = threadIdx.x;
    if (tid < 196) {
        float s = 0.f;
        for (int hh = 0; hh < H_; hh++)
            s += attn[((size_t)(b * H_ + hh) * N_ + (tid + 1)) * N_ + (tid + 1)];
        diag[tid] = s;
    }
    __syncthreads();
    if (tid < 196) {
        float di = diag[tid];
        int rank = 0;
        for (int j = 0; j < 196; j++) {
            float dj = diag[j];
            rank += (dj > di) || (dj == di && j < tid);
        }
        kept[tid] = (rank < NKEPT_) ? 1 : 0;
    }
    __syncthreads();
    if (tid < 196) {
        int mine = kept[tid];
        int pos = 0;
        for (int j = 0; j < tid; j++) pos += (kept[j] == mine);
        if (mine) ik[b * K_ + 1 + pos] = tid + 1;
        else      ie[b * R_ + pos]     = tid + 1;
    }
    if (tid == 0) ik[b * K_] = 0;
}

// ---------------- propagation ----------------
__global__ void propagate_kernel(const float* __restrict__ attn, const float* __restrict__ x1,
                                 const int* __restrict__ ikg, const int* __restrict__ ieg,
                                 float* __restrict__ x2)
{
    extern __shared__ float sm[];
    float* ws = sm;
    float* xe = sm + K_ * R_;
    __shared__ int ik[K_], ie[R_];
    __shared__ int cnt;
    int bh = blockIdx.x;
    int b = bh / H_, hh = bh % H_;
    int tid = threadIdx.x;
    if (tid < K_) ik[tid] = ikg[b * K_ + tid];
    if (tid < R_) ie[tid] = ieg[b * R_ + tid];
    __syncthreads();
    const float* ablk = attn + (size_t)bh * N_ * N_;
    for (int idx = tid; idx < K_ * R_; idx += 256) {
        int k = idx / R_, e = idx - k * R_;
        ws[idx] = ablk[(size_t)ik[k] * N_ + ie[e]];
    }
    for (int idx = tid; idx < R_ * 64; idx += 256) {
        int e = idx >> 6, d = idx & 63;
        xe[idx] = x1[(size_t)(b * N_ + ie[e]) * 768 + hh * 64 + d];
    }
    __syncthreads();

    unsigned lo = 0u, hi = 0x7f7fffffu;
    while (lo < hi) {
        unsigned mid = lo + ((hi - lo + 1) >> 1);
        if (tid == 0) cnt = 0;
        __syncthreads();
        int local = 0;
        for (int i = tid; i < K_ * R_; i += 256)
            local += (__float_as_uint(ws[i]) >= mid);
        for (int off = 16; off; off >>= 1) local += __shfl_xor_sync(0xffffffffu, local, off);
        if ((tid & 31) == 0) atomicAdd(&cnt, local);
        __syncthreads();
        int c = cnt;
        __syncthreads();
        if (c >= THRK_) lo = mid; else hi = mid - 1;
    }
    float thr = __uint_as_float(lo);

    for (int p = tid; p < K_ * 64; p += 256) {
        int k = p >> 6, d = p & 63;
        const float* wr = ws + k * R_;
        float acc = 0.f;
#pragma unroll 2
        for (int e = 0; e < R_; e++) {
            float wv = wr[e];
            wv = (wv >= thr) ? wv : 0.f;
            acc = fmaf(wv, xe[e * 64 + d], acc);
        }
        x2[(size_t)(b * K_ + k) * 768 + hh * 64 + d] =
            x1[(size_t)(b * N_ + ik[k]) * 768 + hh * 64 + d] + ALPHA_ * acc;
    }
}

// ---------------- host ----------------
extern "C" void kernel_launch(void* const* d_in, const int* in_sizes, int n_in,
                              void* d_out, int out_size)
{
    const float* x     = (const float*)d_in[0];
    const float* n1g   = (const float*)d_in[1];
    const float* n1b   = (const float*)d_in[2];
    const float* qkvw  = (const float*)d_in[3];
    const float* projw = (const float*)d_in[4];
    const float* projb = (const float*)d_in[5];
    const float* n2g   = (const float*)d_in[6];
    const float* n2b   = (const float*)d_in[7];
    const float* fc1w  = (const float*)d_in[8];
    const float* fc1b  = (const float*)d_in[9];
    const float* fc2w  = (const float*)d_in[10];
    const float* fc2b  = (const float*)d_in[11];
    float* out = (float*)d_out;

    float *qkv, *attn, *x1, *x2;
    int *ik, *ie;
    unsigned *hh, *hl, *wqkvh, *wqkvl, *wprojh, *wfc1h, *wfc2h, *aoh, *h2h, *mlph;
    cudaGetSymbolAddress((void**)&qkv,  g_qkv);
    cudaGetSymbolAddress((void**)&attn, g_attn);
    cudaGetSymbolAddress((void**)&x1,   g_x1);
    cudaGetSymbolAddress((void**)&x2,   g_x2);
    cudaGetSymbolAddress((void**)&ik,   g_ik);
    cudaGetSymbolAddress((void**)&ie,   g_ie);
    cudaGetSymbolAddress((void**)&hh,   g_hh);
    cudaGetSymbolAddress((void**)&hl,   g_hl);
    cudaGetSymbolAddress((void**)&wqkvh, g_wqkvh);
    cudaGetSymbolAddress((void**)&wqkvl, g_wqkvl);
    cudaGetSymbolAddress((void**)&wprojh, g_wprojh);
    cudaGetSymbolAddress((void**)&wfc1h, g_wfc1h);
    cudaGetSymbolAddress((void**)&wfc2h, g_wfc2h);
    cudaGetSymbolAddress((void**)&aoh,  g_aoh);
    cudaGetSymbolAddress((void**)&h2h,  g_h2h);
    cudaGetSymbolAddress((void**)&mlph, g_mlph);

    const int PROP_SMEM = (K_ * R_ + R_ * 64) * 4;
    cudaFuncSetAttribute(propagate_kernel, cudaFuncAttributeMaxDynamicSharedMemorySize, PROP_SMEM);
    const int SMEM_SPLIT = (HASZ + HBSZ) * 2 * 4;   // 27136
    const int SMEM_PLAIN = (HASZ + HBSZ) * 4;       // 13568

    // 0. weight packing
    cvtw_pack<1><<<(384 * 2304 + 255) / 256, 256>>>(qkvw, wqkvh, wqkvl, 2304, 384 * 2304);
    cvtw_pack<0><<<(384 * 768 + 255) / 256, 256>>>(projw, wprojh, nullptr, 768, 384 * 768);
    cvtw_pack<0><<<(384 * 3072 + 255) / 256, 256>>>(fc1w, wfc1h, nullptr, 3072, 384 * 3072);
    cvtw_pack<0><<<(1536 * 768 + 255) / 256, 256>>>(fc2w, wfc2h, nullptr, 768, 1536 * 768);

    // 1. LN1 -> packed fp16 hi/lo
    ln_pack_kernel<1><<<B_ * N_, 256>>>(x, n1g, n1b, hh, hl);
    // 2. QKV GEMM (split-fp16: ~21-bit mantissa, rank-safe)
    hgemm_kernel<1, false, false, false, false><<<dim3(18, 197), 256, SMEM_SPLIT>>>(
        hh, hl, wqkvh, wqkvl, nullptr, nullptr, qkv, nullptr, 2304, C_, 2304);
    // 3. scores
    score_kernel<<<dim3(B_ * H_, 4, 4), 256>>>(qkv, attn);
    // 4. softmax
    softmax_kernel<<<(B_ * H_ * N_ + 7) / 8, 256>>>(attn);
    // 5. attn @ V -> packed fp16 ao
    av_kernel<<<dim3(B_ * H_, 4), 256>>>(qkv, attn, aoh);
    // 6. proj + bias + residual (plain fp16)
    hgemm_kernel<0, false, true, true, false><<<dim3(6, 197), 256, SMEM_PLAIN>>>(
        aoh, nullptr, wprojh, nullptr, projb, x, x1, nullptr, C_, C_, C_);
    // 7. selection
    select_kernel<<<B_, 256>>>(attn, ik, ie);
    // 8. propagation
    propagate_kernel<<<B_ * H_, 256, PROP_SMEM>>>(attn, x1, ik, ie, x2);
    // 9. LN2 -> packed fp16
    ln_pack_kernel<0><<<B_ * K_, 256>>>(x2, n2g, n2b, h2h, nullptr);
    // 10. fc1 + gelu -> packed fp16 mlp
    hgemm_kernel<0, true, true, false, true><<<dim3(24, 99), 256, SMEM_PLAIN>>>(
        h2h, nullptr, wfc1h, nullptr, fc1b, nullptr, nullptr, mlph, 4 * C_, C_, 0);
    // 11. fc2 + residual -> out
    hgemm_kernel<0, false, true, true, false><<<dim3(6, 99), 256, SMEM_PLAIN>>>(
        mlph, nullptr, wfc2h, nullptr, fc2b, x2, out, nullptr, C_, 4 * C_, C_);
}